// round 3
// baseline (speedup 1.0000x reference)
#include <cuda_runtime.h>
#include <math.h>

#define NN    4096
#define DIN   768
#define CD    128
#define HH1   4
#define F1    512
#define CHUNK 256
#define NCH   (NN/CHUNK)   // 16

// ---------------- device scratch (no allocs allowed) ----------------
__device__ float g_h1[NN*F1];
__device__ float g_x1[NN*F1];
__device__ float g_h2[NN*CD];
__device__ float g_x2[NN*CD];

__device__ float g_s1[HH1*NN], g_t1[HH1*NN], g_ss1[HH1*NN];
__device__ float g_w0_1[HH1*NN], g_w1_1[HH1*NN], g_z0_1[HH1*NN], g_z1_1[HH1*NN];
__device__ int   g_si1[HH1*NN];
__device__ int   g_k1[HH1*NN];
__device__ float g_I0_1[HH1*NN*CD], g_S1_1[HH1*NN*CD];
__device__ float g_O0_1[HH1*NCH*CD], g_O1_1[HH1*NCH*CD];

__device__ float g_s2[NN], g_t2[NN], g_ss2[NN];
__device__ float g_w0_2[NN], g_w1_2[NN], g_z0_2[NN], g_z1_2[NN];
__device__ int   g_si2[NN];
__device__ int   g_k2[NN];
__device__ float g_I0_2[NN*CD], g_S1_2[NN*CD];
__device__ float g_O0_2[NCH*CD], g_O1_2[NCH*CD];

__device__ float g_part[32*CD], g_m[CD];

// ---------------- f32x2 helpers (FFMA2 via PTX) ----------------
typedef unsigned long long ull;

__device__ __forceinline__ ull fma2(ull a, ull b, ull c) {
    ull d;
    asm("fma.rn.f32x2 %0, %1, %2, %3;" : "=l"(d) : "l"(a), "l"(b), "l"(c));
    return d;
}
__device__ __forceinline__ ull pack2(float x, float y) {
    ull d;
    unsigned xi = __float_as_uint(x), yi = __float_as_uint(y);
    asm("mov.b64 %0, {%1, %2};" : "=l"(d) : "r"(xi), "r"(yi));
    return d;
}
__device__ __forceinline__ void unpack2(ull d, float& x, float& y) {
    unsigned lo, hi;
    asm("mov.b64 {%0, %1}, %2;" : "=r"(lo), "=r"(hi) : "l"(d));
    x = __uint_as_float(lo); y = __uint_as_float(hi);
}

__device__ __forceinline__ float elu1(float x) { return x > 0.f ? x : expm1f(x); }

// ---------------- SGEMM: C[M,N] = A[M,K] * B[K,N], fp32 with f32x2 micro-kernel ----
// Requirements: BM*BK == 1024, BK*BN == 1024, 256 threads, dims divisible.
template<int BM, int BN, int BK, int TM, int TN>
__global__ void __launch_bounds__(256)
sgemm_kernel(const float* __restrict__ Aopt, const float* __restrict__ B,
             int layer, int M, int N, int K) {
    const float* A = (layer == 0) ? Aopt : g_x1;
    float*       C = (layer == 0) ? g_h1 : g_h2;

    __shared__ __align__(16) float As[BK][BM];
    __shared__ __align__(16) float Bs[BK][BN];

    const int tid = threadIdx.x;
    const int bm = blockIdx.x * BM, bn = blockIdx.y * BN;

    constexpr int TN2 = TN / 2;
    constexpr int TNT = BN / TN;                 // threads along n
    const int m0 = (tid / TNT) * TM;
    const int n0 = (tid % TNT) * TN;

    constexpr int AK4 = BK / 4;
    const int a_row = tid / AK4, a_k4 = tid % AK4;
    constexpr int BN4 = BN / 4;
    const int b_row = tid / BN4, b_n4 = tid % BN4;

    ull acc[TM][TN2];
#pragma unroll
    for (int i = 0; i < TM; i++)
#pragma unroll
        for (int j = 0; j < TN2; j++) acc[i][j] = 0ull;

    for (int k0 = 0; k0 < K; k0 += BK) {
        float4 av = *reinterpret_cast<const float4*>(&A[(bm + a_row) * K + k0 + a_k4 * 4]);
        float4 bv = *reinterpret_cast<const float4*>(&B[(k0 + b_row) * N + bn + b_n4 * 4]);
        __syncthreads();
        As[a_k4 * 4 + 0][a_row] = av.x;
        As[a_k4 * 4 + 1][a_row] = av.y;
        As[a_k4 * 4 + 2][a_row] = av.z;
        As[a_k4 * 4 + 3][a_row] = av.w;
        *reinterpret_cast<float4*>(&Bs[b_row][b_n4 * 4]) = bv;
        __syncthreads();

#pragma unroll
        for (int kk = 0; kk < BK; kk++) {
            float a[TM];
            if constexpr (TM == 2) {
                float2 t2 = *reinterpret_cast<const float2*>(&As[kk][m0]);
                a[0] = t2.x; a[1] = t2.y;
            } else {
#pragma unroll
                for (int i = 0; i < TM; i += 4) {
                    float4 t4 = *reinterpret_cast<const float4*>(&As[kk][m0 + i]);
                    a[i] = t4.x; a[i + 1] = t4.y; a[i + 2] = t4.z; a[i + 3] = t4.w;
                }
            }
            ull b2[TN2];
            const ull* bp = reinterpret_cast<const ull*>(&Bs[kk][n0]);
#pragma unroll
            for (int j = 0; j < TN2; j++) b2[j] = bp[j];
#pragma unroll
            for (int i = 0; i < TM; i++) {
                ull a2 = pack2(a[i], a[i]);
#pragma unroll
                for (int j = 0; j < TN2; j++) acc[i][j] = fma2(a2, b2[j], acc[i][j]);
            }
        }
    }

#pragma unroll
    for (int i = 0; i < TM; i++) {
#pragma unroll
        for (int j4 = 0; j4 < TN / 4; j4++) {
            float x0, x1, x2, x3;
            unpack2(acc[i][2 * j4 + 0], x0, x1);
            unpack2(acc[i][2 * j4 + 1], x2, x3);
            float4 v = make_float4(x0, x1, x2, x3);
            *reinterpret_cast<float4*>(&C[(bm + m0 + i) * N + bn + n0 + 4 * j4]) = v;
        }
    }
}

// ---------------- s,t = <h, att_src>, <h, att_dst> per (node, head) ----------------
__global__ void st_kernel(int layer, const float* __restrict__ asrc,
                          const float* __restrict__ adst, int H, int F) {
    const float* h = (layer == 0) ? g_h1 : g_h2;
    float* s = (layer == 0) ? g_s1 : g_s2;
    float* t = (layer == 0) ? g_t1 : g_t2;

    int w = (blockIdx.x * blockDim.x + threadIdx.x) >> 5;
    int lane = threadIdx.x & 31;
    int node = w / H, head = w % H;
    if (node >= NN) return;

    const float* hr = h + node * F + head * CD;
    const float* as = asrc + head * CD;
    const float* ad = adst + head * CD;
    float sv = 0.f, tv = 0.f;
#pragma unroll
    for (int c = lane; c < CD; c += 32) {
        float hv = hr[c];
        sv = fmaf(hv, as[c], sv);
        tv = fmaf(hv, ad[c], tv);
    }
#pragma unroll
    for (int o = 16; o; o >>= 1) {
        sv += __shfl_xor_sync(0xffffffffu, sv, o);
        tv += __shfl_xor_sync(0xffffffffu, tv, o);
    }
    if (lane == 0) {
        s[head * NN + node] = sv;
        t[head * NN + node] = tv;
    }
}

// ---------------- bitonic sort of s per head (key asc + payload index) ----------------
__global__ void sort_kernel(int layer) {
    const float* s = (layer == 0) ? g_s1 : g_s2;
    float* ss = (layer == 0) ? g_ss1 : g_ss2;
    int*   si = (layer == 0) ? g_si1 : g_si2;
    int h = blockIdx.x;

    __shared__ float key[NN];
    __shared__ int   val[NN];
    for (int i = threadIdx.x; i < NN; i += blockDim.x) { key[i] = s[h * NN + i]; val[i] = i; }
    __syncthreads();

    for (int k = 2; k <= NN; k <<= 1) {
        for (int j = k >> 1; j > 0; j >>= 1) {
            for (int i = threadIdx.x; i < NN; i += blockDim.x) {
                int ixj = i ^ j;
                if (ixj > i) {
                    float a = key[i], b = key[ixj];
                    bool up = ((i & k) == 0);
                    bool sw = up ? (a > b) : (a < b);
                    if (sw) {
                        key[i] = b; key[ixj] = a;
                        int tv = val[i]; val[i] = val[ixj]; val[ixj] = tv;
                    }
                }
            }
            __syncthreads();
        }
    }
    for (int i = threadIdx.x; i < NN; i += blockDim.x) {
        ss[h * NN + i] = key[i];
        si[h * NN + i] = val[i];
    }
}

// ---------------- scalar weight scans: w0=exp(0.2 s) prefix, w1=exp(s) suffix -------
__device__ __forceinline__ void scan4096(float* buf, int tid) {
    for (int off = 1; off < NN; off <<= 1) {
        float v[4];
#pragma unroll
        for (int e = 0; e < 4; e++) {
            int i = tid + e * 1024;
            v[e] = buf[i] + ((i >= off) ? buf[i - off] : 0.f);
        }
        __syncthreads();
#pragma unroll
        for (int e = 0; e < 4; e++) buf[tid + e * 1024] = v[e];
        __syncthreads();
    }
}

__global__ void zscan_kernel(int layer) {
    const float* ss = (layer == 0) ? g_ss1 : g_ss2;
    float* w0 = (layer == 0) ? g_w0_1 : g_w0_2;
    float* w1 = (layer == 0) ? g_w1_1 : g_w1_2;
    float* z0 = (layer == 0) ? g_z0_1 : g_z0_2;
    float* z1 = (layer == 0) ? g_z1_1 : g_z1_2;
    int h = blockIdx.x, tid = threadIdx.x;

    __shared__ float buf[NN];
    // prefix of w0 (ascending)
    for (int i = tid; i < NN; i += 1024) {
        float w = expf(0.2f * ss[h * NN + i]);
        w0[h * NN + i] = w;
        buf[i] = w;
    }
    __syncthreads();
    scan4096(buf, tid);
    for (int i = tid; i < NN; i += 1024) z0[h * NN + i] = buf[i];
    __syncthreads();
    // suffix of w1 (load reversed, scan, write reversed)
    for (int i = tid; i < NN; i += 1024) {
        float w = expf(ss[h * NN + (NN - 1 - i)]);
        w1[h * NN + (NN - 1 - i)] = w;
        buf[i] = w;
    }
    __syncthreads();
    scan4096(buf, tid);
    for (int i = tid; i < NN; i += 1024) z1[h * NN + (NN - 1 - i)] = buf[i];
}

// ---------------- chunked vector scans of w0*h (prefix) and w1*h (suffix) ----------
// Staged indices/weights in shared; 16-wide independent gather batches (MLP~16)
// ahead of the serial fma chain.
__global__ void __launch_bounds__(CD)
passA_kernel(int layer, int F) {
    const float* h  = (layer == 0) ? g_h1 : g_h2;
    const int*   si = (layer == 0) ? g_si1 : g_si2;
    const float* w0 = (layer == 0) ? g_w0_1 : g_w0_2;
    const float* w1 = (layer == 0) ? g_w1_1 : g_w1_2;
    float* I0 = (layer == 0) ? g_I0_1 : g_I0_2;
    float* S1 = (layer == 0) ? g_S1_1 : g_S1_2;

    const int chunk = blockIdx.x, head = blockIdx.y, dir = blockIdx.z;
    const int c = threadIdx.x;
    const int base = head * NN + chunk * CHUNK;

    __shared__ int   sj[CHUNK];
    __shared__ float sw[CHUNK];
    const float* wsel = (dir == 0) ? w0 : w1;
    for (int r = threadIdx.x; r < CHUNK; r += blockDim.x) {
        sj[r] = si[base + r] * F + head * CD;
        sw[r] = wsel[base + r];
    }
    __syncthreads();

    float acc = 0.f;
    if (dir == 0) {
        float* dst = I0 + (size_t)base * CD + c;
        for (int rr = 0; rr < CHUNK; rr += 16) {
            float v[16];
#pragma unroll
            for (int u = 0; u < 16; u++) v[u] = __ldg(&h[sj[rr + u] + c]);
#pragma unroll
            for (int u = 0; u < 16; u++) {
                acc = fmaf(sw[rr + u], v[u], acc);
                dst[(size_t)(rr + u) * CD] = acc;
            }
        }
    } else {
        float* dst = S1 + (size_t)base * CD + c;
        for (int rr = CHUNK - 16; rr >= 0; rr -= 16) {
            float v[16];
#pragma unroll
            for (int u = 15; u >= 0; u--) v[u] = __ldg(&h[sj[rr + u] + c]);
#pragma unroll
            for (int u = 15; u >= 0; u--) {
                acc = fmaf(sw[rr + u], v[u], acc);
                dst[(size_t)(rr + u) * CD] = acc;
            }
        }
    }
}

// ---------------- cross-chunk offsets ----------------
__global__ void passB_kernel(int layer) {
    const float* I0 = (layer == 0) ? g_I0_1 : g_I0_2;
    const float* S1 = (layer == 0) ? g_S1_1 : g_S1_2;
    float* O0 = (layer == 0) ? g_O0_1 : g_O0_2;
    float* O1 = (layer == 0) ? g_O1_1 : g_O1_2;

    int head = blockIdx.x, c = threadIdx.x;
    float acc = 0.f;
    for (int ch = 0; ch < NCH; ch++) {
        O0[(head * NCH + ch) * CD + c] = acc;
        acc += I0[(head * NN + ch * CHUNK + CHUNK - 1) * CD + c];
    }
    acc = 0.f;
    for (int ch = NCH - 1; ch >= 0; ch--) {
        O1[(head * NCH + ch) * CD + c] = acc;
        acc += S1[(head * NN + ch * CHUNK) * CD + c];
    }
}

// ---------------- split point per (head, node): one thread each ----------------
__global__ void ksearch_kernel(int layer, int H) {
    const float* t  = (layer == 0) ? g_t1 : g_t2;
    const float* ss = (layer == 0) ? g_ss1 : g_ss2;
    int* kk = (layer == 0) ? g_k1 : g_k2;

    int idx = blockIdx.x * blockDim.x + threadIdx.x;
    if (idx >= H * NN) return;
    int head = idx / NN;
    const float* ssh = ss + head * NN;
    float tau = -t[idx];
    int lo = 0, hi = NN;
    while (lo < hi) {
        int mid = (lo + hi) >> 1;
        if (ssh[mid] <= tau) lo = mid + 1; else hi = mid;
    }
    kk[idx] = lo;
}

// ---------------- per-dest lookup: 2 table reads -> out + bias + elu ----------------
__global__ void __launch_bounds__(CD)
lookup_kernel(int layer, const float* __restrict__ bias, int F) {
    const float* t  = (layer == 0) ? g_t1 : g_t2;
    const int*   kk = (layer == 0) ? g_k1 : g_k2;
    const float* I0 = (layer == 0) ? g_I0_1 : g_I0_2;
    const float* S1 = (layer == 0) ? g_S1_1 : g_S1_2;
    const float* O0 = (layer == 0) ? g_O0_1 : g_O0_2;
    const float* O1 = (layer == 0) ? g_O1_1 : g_O1_2;
    const float* z0 = (layer == 0) ? g_z0_1 : g_z0_2;
    const float* z1 = (layer == 0) ? g_z1_1 : g_z1_2;
    float* xout = (layer == 0) ? g_x1 : g_x2;

    int head = blockIdx.y, c = threadIdx.x;
    float bv = bias[head * CD + c];

#pragma unroll 2
    for (int u = 0; u < 8; u++) {
        int i = blockIdx.x * 8 + u;
        float tv = t[head * NN + i];
        int k = kk[head * NN + i];

        float A0 = 0.f, z0v = 0.f, A1 = 0.f, z1v = 0.f;
        if (k > 0) {
            A0 = I0[(size_t)(head * NN + k - 1) * CD + c] +
                 O0[(head * NCH + (k - 1) / CHUNK) * CD + c];
            z0v = z0[head * NN + k - 1];
        }
        if (k < NN) {
            A1 = S1[(size_t)(head * NN + k) * CD + c] +
                 O1[(head * NCH + k / CHUNK) * CD + c];
            z1v = z1[head * NN + k];
        }
        float et  = expf(tv);
        float et2 = expf(0.2f * tv);
        float num = et * A1 + et2 * A0;
        float den = et * z1v + et2 * z0v;
        float o = num / den + bv;
        xout[i * F + head * CD + c] = elu1(o);
    }
}

// ---------------- column mean over nodes (deterministic 2-stage) ----------------
__global__ void colpart_kernel() {
    int b = blockIdx.x, c = threadIdx.x;
    float acc = 0.f;
    for (int r = 0; r < NN / 32; r++) acc += g_x2[(b * (NN / 32) + r) * CD + c];
    g_part[b * CD + c] = acc;
}
__global__ void colfinal_kernel() {
    int c = threadIdx.x;
    float acc = 0.f;
    for (int b = 0; b < 32; b++) acc += g_part[b * CD + c];
    g_m[c] = acc * (1.f / (float)NN);
}
__global__ void fc_kernel(const float* __restrict__ fcW, const float* __restrict__ fcb,
                          float* __restrict__ out) {
    int d = blockIdx.x * blockDim.x + threadIdx.x;
    if (d >= DIN) return;
    float acc = fcb[d];
#pragma unroll 8
    for (int c = 0; c < CD; c++) acc = fmaf(g_m[c], fcW[c * DIN + d], acc);
    out[d] = acc;
}

// ---------------- launch ----------------
extern "C" void kernel_launch(void* const* d_in, const int* in_sizes, int n_in,
                              void* d_out, int out_size) {
    const float* X   = (const float*)d_in[0];
    const float* W1  = (const float*)d_in[1];
    const float* as1 = (const float*)d_in[2];
    const float* ad1 = (const float*)d_in[3];
    const float* b1  = (const float*)d_in[4];
    const float* W2  = (const float*)d_in[5];
    const float* as2 = (const float*)d_in[6];
    const float* ad2 = (const float*)d_in[7];
    const float* b2  = (const float*)d_in[8];
    const float* fcW = (const float*)d_in[9];
    const float* fcb = (const float*)d_in[10];
    float* out = (float*)d_out;

    // Layer 1
    sgemm_kernel<128, 128, 8, 4, 16><<<dim3(NN / 128, F1 / 128), 256>>>(X, W1, 0, NN, F1, DIN);
    st_kernel<<<(NN * HH1 * 32) / 256, 256>>>(0, as1, ad1, HH1, F1);
    sort_kernel<<<HH1, 1024>>>(0);
    zscan_kernel<<<HH1, 1024>>>(0);
    passA_kernel<<<dim3(NCH, HH1, 2), CD>>>(0, F1);
    passB_kernel<<<HH1, CD>>>(0);
    ksearch_kernel<<<(HH1 * NN + 255) / 256, 256>>>(0, HH1);
    lookup_kernel<<<dim3(NN / 8, HH1), CD>>>(0, b1, F1);

    // Layer 2
    sgemm_kernel<64, 64, 16, 2, 8><<<dim3(NN / 64, CD / 64), 256>>>(nullptr, W2, 1, NN, CD, F1);
    st_kernel<<<(NN * 1 * 32) / 256, 256>>>(1, as2, ad2, 1, CD);
    sort_kernel<<<1, 1024>>>(1);
    zscan_kernel<<<1, 1024>>>(1);
    passA_kernel<<<dim3(NCH, 1, 2), CD>>>(1, CD);
    passB_kernel<<<1, CD>>>(1);
    ksearch_kernel<<<(NN + 255) / 256, 256>>>(1, 1);
    lookup_kernel<<<dim3(NN / 8, 1), CD>>>(1, b2, CD);

    // Mean + FC
    colpart_kernel<<<32, CD>>>();
    colfinal_kernel<<<1, CD>>>();
    fc_kernel<<<(DIN + 255) / 256, 256>>>(fcW, fcb, out);
}

// round 6
// speedup vs baseline: 1.3214x; 1.3214x over previous
#include <cuda_runtime.h>
#include <math.h>

#define NN    4096
#define DIN   768
#define CD    128
#define HH1   4
#define F1    512
#define CHUNK 256
#define NCH   (NN/CHUNK)   // 16 (passA chunks)
#define SC    1024         // sort chunk size
#define NSC   4            // sort chunks

typedef unsigned long long ull;

// ---------------- device scratch (no allocs allowed) ----------------
__device__ float g_h1[NN*F1];
__device__ float g_x1[NN*F1];
__device__ float g_h2[NN*CD];
__device__ float g_x2[NN*CD];

__device__ float g_s1[HH1*NN], g_t1[HH1*NN], g_ss1[HH1*NN];
__device__ float g_w0_1[HH1*NN], g_w1_1[HH1*NN], g_z0_1[HH1*NN], g_z1_1[HH1*NN];
__device__ int   g_si1[HH1*NN];
__device__ int   g_k1[HH1*NN];
__device__ float g_I0_1[HH1*NN*CD], g_S1_1[HH1*NN*CD];
__device__ float g_O0_1[HH1*NCH*CD], g_O1_1[HH1*NCH*CD];

__device__ float g_s2[NN], g_t2[NN], g_ss2[NN];
__device__ float g_w0_2[NN], g_w1_2[NN], g_z0_2[NN], g_z1_2[NN];
__device__ int   g_si2[NN];
__device__ int   g_k2[NN];
__device__ float g_I0_2[NN*CD], g_S1_2[NN*CD];
__device__ float g_O0_2[NCH*CD], g_O1_2[NCH*CD];

__device__ ull   g_sc[HH1*NN];   // sorted chunks (reused by both layers)

__device__ float g_part[32*CD];

// ---------------- f32x2 helpers (FFMA2 via PTX) ----------------
__device__ __forceinline__ ull fma2(ull a, ull b, ull c) {
    ull d;
    asm("fma.rn.f32x2 %0, %1, %2, %3;" : "=l"(d) : "l"(a), "l"(b), "l"(c));
    return d;
}
__device__ __forceinline__ ull pack2(float x, float y) {
    ull d;
    unsigned xi = __float_as_uint(x), yi = __float_as_uint(y);
    asm("mov.b64 %0, {%1, %2};" : "=l"(d) : "r"(xi), "r"(yi));
    return d;
}
__device__ __forceinline__ void unpack2(ull d, float& x, float& y) {
    unsigned lo, hi;
    asm("mov.b64 {%0, %1}, %2;" : "=r"(lo), "=r"(hi) : "l"(d));
    x = __uint_as_float(lo); y = __uint_as_float(hi);
}
__device__ __forceinline__ float elu1(float x) { return x > 0.f ? x : expm1f(x); }

// ============================================================================
// GEMM + fused s/t epilogue.
// C[M,N] = A[M,K] * B[K,N], fp32, FFMA2 micro-kernel, double-buffered smem.
// BN=128 (== CD) so blockIdx.y == head; epilogue computes s,t dots per row.
// 128 threads; thread tile TM x 16 with interleaved 4-float column groups.
// ============================================================================
template<int BM, int TM>
__global__ void __launch_bounds__(128)
gemm_st_kernel(const float* __restrict__ Aext, const float* __restrict__ B,
               const float* __restrict__ asrc, const float* __restrict__ adst,
               int layer, int M, int N, int K) {
    constexpr int BN = 128, BK = 8;
    const float* A = (layer == 0) ? Aext : g_x1;
    float* C  = (layer == 0) ? g_h1 : g_h2;
    float* gs = (layer == 0) ? g_s1 : g_s2;
    float* gt = (layer == 0) ? g_t1 : g_t2;

    __shared__ __align__(16) float As[2][BK][BM];
    __shared__ __align__(16) float Bs[2][BK][BN];
    __shared__ float red[2][BM][8];

    const int tid = threadIdx.x;
    const int bm = blockIdx.x * BM, bn = blockIdx.y * BN;
    const int head = blockIdx.y;
    const int nt = tid & 7, mt = tid >> 3;
    const int m0 = mt * TM;

    ull acc[TM][4][2];
#pragma unroll
    for (int i = 0; i < TM; i++)
#pragma unroll
        for (int u = 0; u < 4; u++) { acc[i][u][0] = 0ull; acc[i][u][1] = 0ull; }

    float4 areg[2], breg[2];
    const int ar  = (BM == 128) ? tid : (tid & 63);
    const int ah  = (BM == 128) ? 0 : (tid >> 6);
    const int b_row0 = tid >> 5, b_c4 = tid & 31;

    // prefetch tile 0
    {
        if (BM == 128) {
            areg[0] = *reinterpret_cast<const float4*>(&A[(bm + ar) * K + 0]);
            areg[1] = *reinterpret_cast<const float4*>(&A[(bm + ar) * K + 4]);
        } else {
            areg[0] = *reinterpret_cast<const float4*>(&A[(bm + ar) * K + ah * 4]);
        }
        breg[0] = *reinterpret_cast<const float4*>(&B[(b_row0) * N + bn + b_c4 * 4]);
        breg[1] = *reinterpret_cast<const float4*>(&B[(b_row0 + 4) * N + bn + b_c4 * 4]);
    }
    // store tile 0 into buf 0
    {
        if (BM == 128) {
#pragma unroll
            for (int w = 0; w < 4; w++) As[0][w][ar] = (&areg[0].x)[w];
#pragma unroll
            for (int w = 0; w < 4; w++) As[0][4 + w][ar] = (&areg[1].x)[w];
        } else {
#pragma unroll
            for (int w = 0; w < 4; w++) As[0][ah * 4 + w][ar] = (&areg[0].x)[w];
        }
        *reinterpret_cast<float4*>(&Bs[0][b_row0][b_c4 * 4]) = breg[0];
        *reinterpret_cast<float4*>(&Bs[0][b_row0 + 4][b_c4 * 4]) = breg[1];
    }
    __syncthreads();

    const int ktiles = K / BK;
    for (int t = 0; t < ktiles; t++) {
        const int cur = t & 1;
        if (t + 1 < ktiles) {
            const int k0 = (t + 1) * BK;
            if (BM == 128) {
                areg[0] = *reinterpret_cast<const float4*>(&A[(bm + ar) * K + k0]);
                areg[1] = *reinterpret_cast<const float4*>(&A[(bm + ar) * K + k0 + 4]);
            } else {
                areg[0] = *reinterpret_cast<const float4*>(&A[(bm + ar) * K + k0 + ah * 4]);
            }
            breg[0] = *reinterpret_cast<const float4*>(&B[(k0 + b_row0) * N + bn + b_c4 * 4]);
            breg[1] = *reinterpret_cast<const float4*>(&B[(k0 + b_row0 + 4) * N + bn + b_c4 * 4]);
        }
#pragma unroll
        for (int kk = 0; kk < BK; kk++) {
            float a[TM];
            if (TM == 8) {
                float4 t0 = *reinterpret_cast<const float4*>(&As[cur][kk][m0]);
                float4 t1 = *reinterpret_cast<const float4*>(&As[cur][kk][m0 + 4]);
                a[0]=t0.x; a[1]=t0.y; a[2]=t0.z; a[3]=t0.w;
                a[4]=t1.x; a[5]=t1.y; a[6]=t1.z; a[7]=t1.w;
            } else {
                float4 t0 = *reinterpret_cast<const float4*>(&As[cur][kk][m0]);
                a[0]=t0.x; a[1]=t0.y; a[2]=t0.z; a[3]=t0.w;
            }
            ull b2[4][2];
#pragma unroll
            for (int u = 0; u < 4; u++) {
                ulonglong2 bb = *reinterpret_cast<const ulonglong2*>(&Bs[cur][kk][u * 32 + nt * 4]);
                b2[u][0] = bb.x; b2[u][1] = bb.y;
            }
#pragma unroll
            for (int i = 0; i < TM; i++) {
                ull a2 = pack2(a[i], a[i]);
#pragma unroll
                for (int u = 0; u < 4; u++) {
                    acc[i][u][0] = fma2(a2, b2[u][0], acc[i][u][0]);
                    acc[i][u][1] = fma2(a2, b2[u][1], acc[i][u][1]);
                }
            }
        }
        if (t + 1 < ktiles) {
            const int nxt = cur ^ 1;
            if (BM == 128) {
#pragma unroll
                for (int w = 0; w < 4; w++) As[nxt][w][ar] = (&areg[0].x)[w];
#pragma unroll
                for (int w = 0; w < 4; w++) As[nxt][4 + w][ar] = (&areg[1].x)[w];
            } else {
#pragma unroll
                for (int w = 0; w < 4; w++) As[nxt][ah * 4 + w][ar] = (&areg[0].x)[w];
            }
            *reinterpret_cast<float4*>(&Bs[nxt][b_row0][b_c4 * 4]) = breg[0];
            *reinterpret_cast<float4*>(&Bs[nxt][b_row0 + 4][b_c4 * 4]) = breg[1];
        }
        __syncthreads();
    }

    // epilogue: store C, fused s/t dot products
    float4 asv[4], adv[4];
#pragma unroll
    for (int u = 0; u < 4; u++) {
        asv[u] = *reinterpret_cast<const float4*>(&asrc[head * CD + u * 32 + nt * 4]);
        adv[u] = *reinterpret_cast<const float4*>(&adst[head * CD + u * 32 + nt * 4]);
    }
    float sp[TM], tp[TM];
#pragma unroll
    for (int i = 0; i < TM; i++) { sp[i] = 0.f; tp[i] = 0.f; }
#pragma unroll
    for (int i = 0; i < TM; i++) {
#pragma unroll
        for (int u = 0; u < 4; u++) {
            float x0, x1, x2, x3;
            unpack2(acc[i][u][0], x0, x1);
            unpack2(acc[i][u][1], x2, x3);
            *reinterpret_cast<float4*>(&C[(bm + m0 + i) * N + bn + u * 32 + nt * 4]) =
                make_float4(x0, x1, x2, x3);
            sp[i] += x0 * asv[u].x + x1 * asv[u].y + x2 * asv[u].z + x3 * asv[u].w;
            tp[i] += x0 * adv[u].x + x1 * adv[u].y + x2 * adv[u].z + x3 * adv[u].w;
        }
    }
#pragma unroll
    for (int i = 0; i < TM; i++) { red[0][m0 + i][nt] = sp[i]; red[1][m0 + i][nt] = tp[i]; }
    __syncthreads();
    if (tid < BM) {
        float s = 0.f, t2 = 0.f;
#pragma unroll
        for (int q = 0; q < 8; q++) { s += red[0][tid][q]; t2 += red[1][tid][q]; }
        gs[head * NN + bm + tid] = s;
        gt[head * NN + bm + tid] = t2;
    }
}

// ============================================================================
// Sort stage 1: bitonic sort of 1024-element chunks (key=transformed s, val=idx)
// packed as ull; in-register handling of j<=2 stages. 256 threads, 4 elems each.
// ============================================================================
__device__ __forceinline__ void cswap(ull& a, ull& b, bool asc) {
    if ((a > b) == asc) { ull t = a; a = b; b = t; }
}

__global__ void __launch_bounds__(256)
sortchunk_kernel(int layer) {
    const float* s = (layer == 0) ? g_s1 : g_s2;
    const int head = blockIdx.y, chunk = blockIdx.x;
    const int tid = threadIdx.x;
    __shared__ ull kv[SC];

    const int gbase = head * NN + chunk * SC;
#pragma unroll
    for (int e = 0; e < 4; e++) {
        int i = tid + e * 256;
        unsigned u = __float_as_uint(s[gbase + i]);
        u = (u & 0x80000000u) ? ~u : (u | 0x80000000u);
        kv[i] = ((ull)u << 32) | (unsigned)(chunk * SC + i);
    }
    __syncthreads();

    // k=2 and k=4 entirely in registers on 4-element groups
    {
        int i0 = 4 * tid;
        ull v0 = kv[i0], v1 = kv[i0 + 1], v2 = kv[i0 + 2], v3 = kv[i0 + 3];
        cswap(v0, v1, true); cswap(v2, v3, false);
        bool asc = ((i0 & 4) == 0);
        cswap(v0, v2, asc); cswap(v1, v3, asc);
        cswap(v0, v1, asc); cswap(v2, v3, asc);
        kv[i0] = v0; kv[i0 + 1] = v1; kv[i0 + 2] = v2; kv[i0 + 3] = v3;
    }
    __syncthreads();

    for (int k = 8; k <= SC; k <<= 1) {
        for (int j = k >> 1; j >= 4; j >>= 1) {
#pragma unroll
            for (int e = 0; e < 4; e++) {
                int i = tid + e * 256;
                if ((i & j) == 0) {
                    int p = i | j;
                    ull a = kv[i], b = kv[p];
                    bool asc = ((i & k) == 0);
                    if ((a > b) == asc) { kv[i] = b; kv[p] = a; }
                }
            }
            __syncthreads();
        }
        // j=2,1 in registers
        {
            int i0 = 4 * tid;
            ull v0 = kv[i0], v1 = kv[i0 + 1], v2 = kv[i0 + 2], v3 = kv[i0 + 3];
            bool asc = ((i0 & k) == 0);
            cswap(v0, v2, asc); cswap(v1, v3, asc);
            cswap(v0, v1, asc); cswap(v2, v3, asc);
            kv[i0] = v0; kv[i0 + 1] = v1; kv[i0 + 2] = v2; kv[i0 + 3] = v3;
        }
        __syncthreads();
    }

#pragma unroll
    for (int e = 0; e < 4; e++) {
        int i = tid + e * 256;
        g_sc[(head * NSC + chunk) * SC + i] = kv[i];
    }
}

// ============================================================================
// Sort stage 2: rank-merge of 4 sorted chunks. Each element's final rank =
// own position + 3 interleaved galloping lower-bound counts (unique ull keys).
// Galloping lower bound: steps SC..1 with pos+step<=SC guard — exact, no OOB.
// ============================================================================
__global__ void __launch_bounds__(256)
merge_kernel(int layer, int H) {
    float* ss = (layer == 0) ? g_ss1 : g_ss2;
    int*   si = (layer == 0) ? g_si1 : g_si2;

    int gid = blockIdx.x * 256 + threadIdx.x;
    if (gid >= H * NN) return;
    int head = gid >> 12;
    int i = gid & (NN - 1);
    int c = i >> 10, p = i & (SC - 1);

    const ull* base = g_sc + (size_t)head * NN;
    ull v = base[c * SC + p];

    const ull* oth[3];
    int cc = 0;
#pragma unroll
    for (int q = 0; q < 4; q++) if (q != c) oth[cc++] = base + q * SC;

    int p0 = 0, p1 = 0, p2 = 0;
#pragma unroll
    for (int step = SC; step >= 1; step >>= 1) {
        bool g0 = (p0 + step <= SC) && (__ldg(&oth[0][p0 + step - 1]) < v);
        bool g1 = (p1 + step <= SC) && (__ldg(&oth[1][p1 + step - 1]) < v);
        bool g2 = (p2 + step <= SC) && (__ldg(&oth[2][p2 + step - 1]) < v);
        if (g0) p0 += step;
        if (g1) p1 += step;
        if (g2) p2 += step;
    }
    int rank = p + p0 + p1 + p2;

    unsigned ku = (unsigned)(v >> 32);
    float f = (ku & 0x80000000u) ? __uint_as_float(ku ^ 0x80000000u)
                                 : __uint_as_float(~ku);
    ss[head * NN + rank] = f;
    si[head * NN + rank] = (int)(v & 0xffffffffu);
}

// ============================================================================
// postsort: per head — w0/w1 weights, inclusive prefix scan z0, inclusive
// suffix scan z1 (shfl-based, no subtraction), and ksearch for all nodes.
// 1024 threads, thread owns 4 consecutive elements.
// ============================================================================
__global__ void __launch_bounds__(1024)
postsort_kernel(int layer) {
    const float* ss = (layer == 0) ? g_ss1 : g_ss2;
    const float* t  = (layer == 0) ? g_t1  : g_t2;
    float* w0 = (layer == 0) ? g_w0_1 : g_w0_2;
    float* w1 = (layer == 0) ? g_w1_1 : g_w1_2;
    float* z0 = (layer == 0) ? g_z0_1 : g_z0_2;
    float* z1 = (layer == 0) ? g_z1_1 : g_z1_2;
    int*   kk = (layer == 0) ? g_k1 : g_k2;

    const int head = blockIdx.x, tid = threadIdx.x;
    const int lane = tid & 31, warp = tid >> 5;
    __shared__ float ssm[NN];
    __shared__ float wsum[32], woff[32];

#pragma unroll
    for (int e = 0; e < 4; e++) ssm[tid + e * 1024] = ss[head * NN + tid + e * 1024];
    __syncthreads();

    const int i0 = 4 * tid;
    float e0 = expf(0.2f * ssm[i0]),     e1 = expf(0.2f * ssm[i0 + 1]);
    float e2 = expf(0.2f * ssm[i0 + 2]), e3 = expf(0.2f * ssm[i0 + 3]);
    float f0 = expf(ssm[i0]),     f1 = expf(ssm[i0 + 1]);
    float f2 = expf(ssm[i0 + 2]), f3 = expf(ssm[i0 + 3]);

    // ---- prefix (w0) ----
    {
        float p0 = e0, p1 = p0 + e1, p2 = p1 + e2, p3 = p2 + e3;
        float x = p3;
#pragma unroll
        for (int o = 1; o < 32; o <<= 1) {
            float y = __shfl_up_sync(0xffffffffu, x, o);
            if (lane >= o) x += y;
        }
        float wexcl = x - p3;
        if (lane == 31) wsum[warp] = x;
        __syncthreads();
        if (warp == 0) {
            float v = wsum[lane];
#pragma unroll
            for (int o = 1; o < 32; o <<= 1) {
                float y = __shfl_up_sync(0xffffffffu, v, o);
                if (lane >= o) v += y;
            }
            woff[lane] = v - wsum[lane];
        }
        __syncthreads();
        float off = woff[warp] + wexcl;
        int gb = head * NN + i0;
        w0[gb] = e0; w0[gb + 1] = e1; w0[gb + 2] = e2; w0[gb + 3] = e3;
        z0[gb] = p0 + off; z0[gb + 1] = p1 + off; z0[gb + 2] = p2 + off; z0[gb + 3] = p3 + off;
    }
    __syncthreads();

    // ---- suffix (w1) ----
    {
        float q3 = f3, q2 = q3 + f2, q1 = q2 + f1, q0 = q1 + f0;
        float x = q0;
#pragma unroll
        for (int o = 1; o < 32; o <<= 1) {
            float y = __shfl_down_sync(0xffffffffu, x, o);
            if (lane + o < 32) x += y;
        }
        float wexcl = x - q0;
        if (lane == 0) wsum[warp] = x;
        __syncthreads();
        if (warp == 0) {
            float v = wsum[lane];
#pragma unroll
            for (int o = 1; o < 32; o <<= 1) {
                float y = __shfl_down_sync(0xffffffffu, v, o);
                if (lane + o < 32) v += y;
            }
            woff[lane] = v - wsum[lane];
        }
        __syncthreads();
        float off = woff[warp] + wexcl;
        int gb = head * NN + i0;
        w1[gb] = f0; w1[gb + 1] = f1; w1[gb + 2] = f2; w1[gb + 3] = f3;
        z1[gb] = q0 + off; z1[gb + 1] = q1 + off; z1[gb + 2] = q2 + off; z1[gb + 3] = q3 + off;
    }
    __syncthreads();

    // ---- ksearch in shared: k = #{ j : ssm[j] <= tau }, galloping (exact) ----
#pragma unroll
    for (int e = 0; e < 4; e++) {
        int node = tid + e * 1024;
        float tau = -t[head * NN + node];
        int pos = 0;
#pragma unroll
        for (int step = NN; step >= 1; step >>= 1) {
            if (pos + step <= NN && ssm[pos + step - 1] <= tau) pos += step;
        }
        kk[head * NN + node] = pos;
    }
}

// ============================================================================
// passA: chunked vector scans of w0*h (prefix) and w1*h (suffix), MLP=16 gathers
// ============================================================================
__global__ void __launch_bounds__(CD)
passA_kernel(int layer, int F) {
    const float* h  = (layer == 0) ? g_h1 : g_h2;
    const int*   si = (layer == 0) ? g_si1 : g_si2;
    const float* w0 = (layer == 0) ? g_w0_1 : g_w0_2;
    const float* w1 = (layer == 0) ? g_w1_1 : g_w1_2;
    float* I0 = (layer == 0) ? g_I0_1 : g_I0_2;
    float* S1 = (layer == 0) ? g_S1_1 : g_S1_2;

    const int chunk = blockIdx.x, head = blockIdx.y, dir = blockIdx.z;
    const int c = threadIdx.x;
    const int base = head * NN + chunk * CHUNK;

    __shared__ int   sj[CHUNK];
    __shared__ float sw[CHUNK];
    const float* wsel = (dir == 0) ? w0 : w1;
    for (int r = threadIdx.x; r < CHUNK; r += blockDim.x) {
        sj[r] = si[base + r] * F + head * CD;
        sw[r] = wsel[base + r];
    }
    __syncthreads();

    float acc = 0.f;
    if (dir == 0) {
        float* dst = I0 + (size_t)base * CD + c;
        for (int rr = 0; rr < CHUNK; rr += 16) {
            float v[16];
#pragma unroll
            for (int u = 0; u < 16; u++) v[u] = __ldg(&h[sj[rr + u] + c]);
#pragma unroll
            for (int u = 0; u < 16; u++) {
                acc = fmaf(sw[rr + u], v[u], acc);
                dst[(size_t)(rr + u) * CD] = acc;
            }
        }
    } else {
        float* dst = S1 + (size_t)base * CD + c;
        for (int rr = CHUNK - 16; rr >= 0; rr -= 16) {
            float v[16];
#pragma unroll
            for (int u = 15; u >= 0; u--) v[u] = __ldg(&h[sj[rr + u] + c]);
#pragma unroll
            for (int u = 15; u >= 0; u--) {
                acc = fmaf(sw[rr + u], v[u], acc);
                dst[(size_t)(rr + u) * CD] = acc;
            }
        }
    }
}

// ---------------- cross-chunk offsets ----------------
__global__ void passB_kernel(int layer) {
    const float* I0 = (layer == 0) ? g_I0_1 : g_I0_2;
    const float* S1 = (layer == 0) ? g_S1_1 : g_S1_2;
    float* O0 = (layer == 0) ? g_O0_1 : g_O0_2;
    float* O1 = (layer == 0) ? g_O1_1 : g_O1_2;

    int head = blockIdx.x, c = threadIdx.x;
    float acc = 0.f;
    for (int ch = 0; ch < NCH; ch++) {
        O0[(head * NCH + ch) * CD + c] = acc;
        acc += I0[(head * NN + ch * CHUNK + CHUNK - 1) * CD + c];
    }
    acc = 0.f;
    for (int ch = NCH - 1; ch >= 0; ch--) {
        O1[(head * NCH + ch) * CD + c] = acc;
        acc += S1[(head * NN + ch * CHUNK) * CD + c];
    }
}

// ---------------- per-dest lookup: 2 table reads -> out + bias + elu ----------------
__global__ void __launch_bounds__(CD)
lookup_kernel(int layer, const float* __restrict__ bias, int F) {
    const float* t  = (layer == 0) ? g_t1 : g_t2;
    const int*   kk = (layer == 0) ? g_k1 : g_k2;
    const float* I0 = (layer == 0) ? g_I0_1 : g_I0_2;
    const float* S1 = (layer == 0) ? g_S1_1 : g_S1_2;
    const float* O0 = (layer == 0) ? g_O0_1 : g_O0_2;
    const float* O1 = (layer == 0) ? g_O1_1 : g_O1_2;
    const float* z0 = (layer == 0) ? g_z0_1 : g_z0_2;
    const float* z1 = (layer == 0) ? g_z1_1 : g_z1_2;
    float* xout = (layer == 0) ? g_x1 : g_x2;

    int head = blockIdx.y, c = threadIdx.x;
    float bv = bias[head * CD + c];

#pragma unroll 2
    for (int u = 0; u < 8; u++) {
        int i = blockIdx.x * 8 + u;
        float tv = t[head * NN + i];
        int k = kk[head * NN + i];

        float A0 = 0.f, z0v = 0.f, A1 = 0.f, z1v = 0.f;
        if (k > 0) {
            A0 = I0[(size_t)(head * NN + k - 1) * CD + c] +
                 O0[(head * NCH + (k - 1) / CHUNK) * CD + c];
            z0v = z0[head * NN + k - 1];
        }
        if (k < NN) {
            A1 = S1[(size_t)(head * NN + k) * CD + c] +
                 O1[(head * NCH + k / CHUNK) * CD + c];
            z1v = z1[head * NN + k];
        }
        float et  = expf(tv);
        float et2 = expf(0.2f * tv);
        float num = et * A1 + et2 * A0;
        float den = et * z1v + et2 * z0v;
        float o = num / den + bv;
        xout[i * F + head * CD + c] = elu1(o);
    }
}

// ---------------- column mean over nodes + FC (fused final) ----------------
__global__ void colpart_kernel() {
    int b = blockIdx.x, c = threadIdx.x;
    float acc = 0.f;
    for (int r = 0; r < NN / 32; r++) acc += g_x2[(b * (NN / 32) + r) * CD + c];
    g_part[b * CD + c] = acc;
}
__global__ void __launch_bounds__(DIN)
colfinal_fc_kernel(const float* __restrict__ fcW, const float* __restrict__ fcb,
                   float* __restrict__ out) {
    __shared__ float m[CD];
    int tid = threadIdx.x;
    if (tid < CD) {
        float a = 0.f;
        for (int b = 0; b < 32; b++) a += g_part[b * CD + tid];
        m[tid] = a * (1.f / (float)NN);
    }
    __syncthreads();
    if (tid < DIN) {
        float acc = fcb[tid];
#pragma unroll 8
        for (int c = 0; c < CD; c++) acc = fmaf(m[c], fcW[c * DIN + tid], acc);
        out[tid] = acc;
    }
}

// ---------------- launch ----------------
extern "C" void kernel_launch(void* const* d_in, const int* in_sizes, int n_in,
                              void* d_out, int out_size) {
    const float* X   = (const float*)d_in[0];
    const float* W1  = (const float*)d_in[1];
    const float* as1 = (const float*)d_in[2];
    const float* ad1 = (const float*)d_in[3];
    const float* b1  = (const float*)d_in[4];
    const float* W2  = (const float*)d_in[5];
    const float* as2 = (const float*)d_in[6];
    const float* ad2 = (const float*)d_in[7];
    const float* b2  = (const float*)d_in[8];
    const float* fcW = (const float*)d_in[9];
    const float* fcb = (const float*)d_in[10];
    float* out = (float*)d_out;

    // Layer 1: M=4096, K=768, N=512
    gemm_st_kernel<128, 8><<<dim3(NN / 128, F1 / 128), 128>>>(X, W1, as1, ad1, 0, NN, F1, DIN);
    sortchunk_kernel<<<dim3(NSC, HH1), 256>>>(0);
    merge_kernel<<<(HH1 * NN) / 256, 256>>>(0, HH1);
    postsort_kernel<<<HH1, 1024>>>(0);
    passA_kernel<<<dim3(NCH, HH1, 2), CD>>>(0, F1);
    passB_kernel<<<HH1, CD>>>(0);
    lookup_kernel<<<dim3(NN / 8, HH1), CD>>>(0, b1, F1);

    // Layer 2: M=4096, K=512, N=128
    gemm_st_kernel<64, 4><<<dim3(NN / 64, 1), 128>>>(nullptr, W2, as2, ad2, 1, NN, CD, F1);
    sortchunk_kernel<<<dim3(NSC, 1), 256>>>(1);
    merge_kernel<<<NN / 256, 256>>>(1, 1);
    postsort_kernel<<<1, 1024>>>(1);
    passA_kernel<<<dim3(NCH, 1, 2), CD>>>(1, CD);
    passB_kernel<<<1, CD>>>(1);
    lookup_kernel<<<dim3(NN / 8, 1), CD>>>(1, b2, CD);

    // Mean + FC
    colpart_kernel<<<32, CD>>>();
    colfinal_fc_kernel<<<1, DIN>>>(fcW, fcb, out);
}

// round 8
// speedup vs baseline: 1.9731x; 1.4932x over previous
#include <cuda_runtime.h>
#include <math.h>

#define NN    4096
#define DIN   768
#define CD    128
#define HH1   4
#define F1    512
#define CHUNK 256
#define NCH   (NN/CHUNK)   // 16 (passA chunks)
#define SC    1024         // sort chunk size
#define NSC   4            // sort chunks

typedef unsigned long long ull;

// ---------------- device scratch (no allocs allowed) ----------------
__device__ float g_h1[NN*F1];
__device__ float g_x1[NN*F1];
__device__ float g_h2[NN*CD];
__device__ float g_x2[NN*CD];

__device__ float g_s1[HH1*NN], g_t1[HH1*NN], g_ss1[HH1*NN];
__device__ float g_w0_1[HH1*NN], g_w1_1[HH1*NN], g_z0_1[HH1*NN], g_z1_1[HH1*NN];
__device__ int   g_si1[HH1*NN];
__device__ int   g_k1[HH1*NN];
__device__ float g_I0_1[HH1*NN*CD], g_S1_1[HH1*NN*CD];
__device__ float g_O0_1[HH1*NCH*CD], g_O1_1[HH1*NCH*CD];

__device__ float g_s2[NN], g_t2[NN], g_ss2[NN];
__device__ float g_w0_2[NN], g_w1_2[NN], g_z0_2[NN], g_z1_2[NN];
__device__ int   g_si2[NN];
__device__ int   g_k2[NN];
__device__ float g_I0_2[NN*CD], g_S1_2[NN*CD];
__device__ float g_O0_2[NCH*CD], g_O1_2[NCH*CD];

__device__ ull   g_sc[HH1*NN];   // sorted chunks (reused by both layers)

__device__ float g_part[32*CD];

// ---------------- f32x2 helpers (FFMA2 via PTX) ----------------
__device__ __forceinline__ ull fma2(ull a, ull b, ull c) {
    ull d;
    asm("fma.rn.f32x2 %0, %1, %2, %3;" : "=l"(d) : "l"(a), "l"(b), "l"(c));
    return d;
}
__device__ __forceinline__ ull pack2(float x, float y) {
    ull d;
    unsigned xi = __float_as_uint(x), yi = __float_as_uint(y);
    asm("mov.b64 %0, {%1, %2};" : "=l"(d) : "r"(xi), "r"(yi));
    return d;
}
__device__ __forceinline__ void unpack2(ull d, float& x, float& y) {
    unsigned lo, hi;
    asm("mov.b64 {%0, %1}, %2;" : "=r"(lo), "=r"(hi) : "l"(d));
    x = __uint_as_float(lo); y = __uint_as_float(hi);
}
__device__ __forceinline__ float elu1(float x) { return x > 0.f ? x : expm1f(x); }

// ============================================================================
// GEMM + fused s/t epilogue. 256 threads, 2 warps/SMSP.
// C[M,N] = A[M,K]*B[K,N]; BN=128 (==CD) so blockIdx.y==head.
// Thread grid 16(m)x16(n); thread tile TM x 8; BK=16; double-buffered smem.
// BM = 16*TM. s/t dots reduced via shfl (16-lane halves).
// ============================================================================
template<int TM>
__global__ void __launch_bounds__(256)
gemm_st_kernel(const float* __restrict__ Aext, const float* __restrict__ B,
               const float* __restrict__ asrc, const float* __restrict__ adst,
               int layer, int M, int N, int K) {
    constexpr int BN = 128, BK = 16;
    constexpr int BM = 16 * TM;
    constexpr int ASTRIDE = BM + 4;            // pad keeps 16B alignment (BM mult of 16)
    constexpr int NA = (BM * 4 + 255) / 256;   // A float4 loads per thread
    const float* A = (layer == 0) ? Aext : g_x1;
    float* C  = (layer == 0) ? g_h1 : g_h2;
    float* gs = (layer == 0) ? g_s1 : g_s2;
    float* gt = (layer == 0) ? g_t1 : g_t2;

    __shared__ __align__(16) float As[2][BK][ASTRIDE];
    __shared__ __align__(16) float Bs[2][BK][BN];

    const int tid = threadIdx.x;
    const int bm = blockIdx.x * BM, bn = blockIdx.y * BN;
    const int head = blockIdx.y;
    const int nt = tid & 15, mt = tid >> 4;
    const int m0 = mt * TM;

    ull acc[TM][4];
#pragma unroll
    for (int i = 0; i < TM; i++)
#pragma unroll
        for (int u = 0; u < 4; u++) acc[i][u] = 0ull;

    float4 apre[NA], bpre[2];

    // prefetch tile 0
#pragma unroll
    for (int j = 0; j < NA; j++) {
        int idx = tid + j * 256;
        if (idx < BM * 4) {
            int row = idx >> 2, c4 = idx & 3;
            apre[j] = *reinterpret_cast<const float4*>(&A[(bm + row) * K + c4 * 4]);
        }
    }
#pragma unroll
    for (int j = 0; j < 2; j++) {
        int idx = tid + j * 256;
        int row = idx >> 5, c4 = idx & 31;
        bpre[j] = *reinterpret_cast<const float4*>(&B[row * N + bn + c4 * 4]);
    }
    // store tile 0
#pragma unroll
    for (int j = 0; j < NA; j++) {
        int idx = tid + j * 256;
        if (idx < BM * 4) {
            int row = idx >> 2, c4 = idx & 3;
#pragma unroll
            for (int w = 0; w < 4; w++) As[0][c4 * 4 + w][row] = (&apre[j].x)[w];
        }
    }
#pragma unroll
    for (int j = 0; j < 2; j++) {
        int idx = tid + j * 256;
        int row = idx >> 5, c4 = idx & 31;
        *reinterpret_cast<float4*>(&Bs[0][row][c4 * 4]) = bpre[j];
    }
    __syncthreads();

    const int ktiles = K / BK;
    for (int t = 0; t < ktiles; t++) {
        const int cur = t & 1;
        if (t + 1 < ktiles) {
            const int k0 = (t + 1) * BK;
#pragma unroll
            for (int j = 0; j < NA; j++) {
                int idx = tid + j * 256;
                if (idx < BM * 4) {
                    int row = idx >> 2, c4 = idx & 3;
                    apre[j] = *reinterpret_cast<const float4*>(&A[(bm + row) * K + k0 + c4 * 4]);
                }
            }
#pragma unroll
            for (int j = 0; j < 2; j++) {
                int idx = tid + j * 256;
                int row = idx >> 5, c4 = idx & 31;
                bpre[j] = *reinterpret_cast<const float4*>(&B[(k0 + row) * N + bn + c4 * 4]);
            }
        }
#pragma unroll
        for (int kk = 0; kk < BK; kk++) {
            float a[TM];
            if (TM == 8) {
                float4 t0 = *reinterpret_cast<const float4*>(&As[cur][kk][m0]);
                float4 t1 = *reinterpret_cast<const float4*>(&As[cur][kk][m0 + 4]);
                a[0]=t0.x; a[1]=t0.y; a[2]=t0.z; a[3]=t0.w;
                a[4]=t1.x; a[5]=t1.y; a[6]=t1.z; a[7]=t1.w;
            } else if (TM == 4) {
                float4 t0 = *reinterpret_cast<const float4*>(&As[cur][kk][m0]);
                a[0]=t0.x; a[1]=t0.y; a[2]=t0.z; a[3]=t0.w;
            } else {
                float2 t0 = *reinterpret_cast<const float2*>(&As[cur][kk][m0]);
                a[0]=t0.x; a[1]=t0.y;
            }
            ulonglong2 bb0 = *reinterpret_cast<const ulonglong2*>(&Bs[cur][kk][nt * 8]);
            ulonglong2 bb1 = *reinterpret_cast<const ulonglong2*>(&Bs[cur][kk][nt * 8 + 4]);
#pragma unroll
            for (int i = 0; i < TM; i++) {
                ull a2 = pack2(a[i], a[i]);
                acc[i][0] = fma2(a2, bb0.x, acc[i][0]);
                acc[i][1] = fma2(a2, bb0.y, acc[i][1]);
                acc[i][2] = fma2(a2, bb1.x, acc[i][2]);
                acc[i][3] = fma2(a2, bb1.y, acc[i][3]);
            }
        }
        if (t + 1 < ktiles) {
            const int nxt = cur ^ 1;
#pragma unroll
            for (int j = 0; j < NA; j++) {
                int idx = tid + j * 256;
                if (idx < BM * 4) {
                    int row = idx >> 2, c4 = idx & 3;
#pragma unroll
                    for (int w = 0; w < 4; w++) As[nxt][c4 * 4 + w][row] = (&apre[j].x)[w];
                }
            }
#pragma unroll
            for (int j = 0; j < 2; j++) {
                int idx = tid + j * 256;
                int row = idx >> 5, c4 = idx & 31;
                *reinterpret_cast<float4*>(&Bs[nxt][row][c4 * 4]) = bpre[j];
            }
        }
        __syncthreads();
    }

    // epilogue: store C + fused s/t dots (shfl-reduced over 16 n-threads)
    float4 asv0 = *reinterpret_cast<const float4*>(&asrc[head * CD + nt * 8]);
    float4 asv1 = *reinterpret_cast<const float4*>(&asrc[head * CD + nt * 8 + 4]);
    float4 adv0 = *reinterpret_cast<const float4*>(&adst[head * CD + nt * 8]);
    float4 adv1 = *reinterpret_cast<const float4*>(&adst[head * CD + nt * 8 + 4]);

#pragma unroll
    for (int i = 0; i < TM; i++) {
        float x0, x1, x2, x3, x4, x5, x6, x7;
        unpack2(acc[i][0], x0, x1);
        unpack2(acc[i][1], x2, x3);
        unpack2(acc[i][2], x4, x5);
        unpack2(acc[i][3], x6, x7);
        *reinterpret_cast<float4*>(&C[(bm + m0 + i) * N + bn + nt * 8]) =
            make_float4(x0, x1, x2, x3);
        *reinterpret_cast<float4*>(&C[(bm + m0 + i) * N + bn + nt * 8 + 4]) =
            make_float4(x4, x5, x6, x7);
        float sp = x0*asv0.x + x1*asv0.y + x2*asv0.z + x3*asv0.w
                 + x4*asv1.x + x5*asv1.y + x6*asv1.z + x7*asv1.w;
        float tp = x0*adv0.x + x1*adv0.y + x2*adv0.z + x3*adv0.w
                 + x4*adv1.x + x5*adv1.y + x6*adv1.z + x7*adv1.w;
#pragma unroll
        for (int o = 1; o < 16; o <<= 1) {
            sp += __shfl_xor_sync(0xffffffffu, sp, o);
            tp += __shfl_xor_sync(0xffffffffu, tp, o);
        }
        if (nt == 0) {
            gs[head * NN + bm + m0 + i] = sp;
            gt[head * NN + bm + m0 + i] = tp;
        }
    }
}

// ============================================================================
// Sort stage 1: bitonic sort of 1024-element chunks (key=transformed s, val=idx)
// ============================================================================
__device__ __forceinline__ void cswap(ull& a, ull& b, bool asc) {
    if ((a > b) == asc) { ull t = a; a = b; b = t; }
}

__global__ void __launch_bounds__(256)
sortchunk_kernel(int layer) {
    const float* s = (layer == 0) ? g_s1 : g_s2;
    const int head = blockIdx.y, chunk = blockIdx.x;
    const int tid = threadIdx.x;
    __shared__ ull kv[SC];

    const int gbase = head * NN + chunk * SC;
#pragma unroll
    for (int e = 0; e < 4; e++) {
        int i = tid + e * 256;
        unsigned u = __float_as_uint(s[gbase + i]);
        u = (u & 0x80000000u) ? ~u : (u | 0x80000000u);
        kv[i] = ((ull)u << 32) | (unsigned)(chunk * SC + i);
    }
    __syncthreads();

    {
        int i0 = 4 * tid;
        ull v0 = kv[i0], v1 = kv[i0 + 1], v2 = kv[i0 + 2], v3 = kv[i0 + 3];
        cswap(v0, v1, true); cswap(v2, v3, false);
        bool asc = ((i0 & 4) == 0);
        cswap(v0, v2, asc); cswap(v1, v3, asc);
        cswap(v0, v1, asc); cswap(v2, v3, asc);
        kv[i0] = v0; kv[i0 + 1] = v1; kv[i0 + 2] = v2; kv[i0 + 3] = v3;
    }
    __syncthreads();

    for (int k = 8; k <= SC; k <<= 1) {
        for (int j = k >> 1; j >= 4; j >>= 1) {
#pragma unroll
            for (int e = 0; e < 4; e++) {
                int i = tid + e * 256;
                if ((i & j) == 0) {
                    int p = i | j;
                    ull a = kv[i], b = kv[p];
                    bool asc = ((i & k) == 0);
                    if ((a > b) == asc) { kv[i] = b; kv[p] = a; }
                }
            }
            __syncthreads();
        }
        {
            int i0 = 4 * tid;
            ull v0 = kv[i0], v1 = kv[i0 + 1], v2 = kv[i0 + 2], v3 = kv[i0 + 3];
            bool asc = ((i0 & k) == 0);
            cswap(v0, v2, asc); cswap(v1, v3, asc);
            cswap(v0, v1, asc); cswap(v2, v3, asc);
            kv[i0] = v0; kv[i0 + 1] = v1; kv[i0 + 2] = v2; kv[i0 + 3] = v3;
        }
        __syncthreads();
    }

#pragma unroll
    for (int e = 0; e < 4; e++) {
        int i = tid + e * 256;
        g_sc[(head * NSC + chunk) * SC + i] = kv[i];
    }
}

// ============================================================================
// Sort stage 2: rank-merge of 4 sorted chunks (galloping lower bound, exact)
// + fused weight computation w0=exp(0.2 s), w1=exp(s).
// ============================================================================
__global__ void __launch_bounds__(256)
merge_kernel(int layer, int H) {
    float* ss = (layer == 0) ? g_ss1 : g_ss2;
    int*   si = (layer == 0) ? g_si1 : g_si2;
    float* w0 = (layer == 0) ? g_w0_1 : g_w0_2;
    float* w1 = (layer == 0) ? g_w1_1 : g_w1_2;

    int gid = blockIdx.x * 256 + threadIdx.x;
    if (gid >= H * NN) return;
    int head = gid >> 12;
    int i = gid & (NN - 1);
    int c = i >> 10, p = i & (SC - 1);

    const ull* base = g_sc + (size_t)head * NN;
    ull v = base[c * SC + p];

    const ull* oth[3];
    int cc = 0;
#pragma unroll
    for (int q = 0; q < 4; q++) if (q != c) oth[cc++] = base + q * SC;

    int p0 = 0, p1 = 0, p2 = 0;
#pragma unroll
    for (int step = SC; step >= 1; step >>= 1) {
        bool g0 = (p0 + step <= SC) && (__ldg(&oth[0][p0 + step - 1]) < v);
        bool g1 = (p1 + step <= SC) && (__ldg(&oth[1][p1 + step - 1]) < v);
        bool g2 = (p2 + step <= SC) && (__ldg(&oth[2][p2 + step - 1]) < v);
        if (g0) p0 += step;
        if (g1) p1 += step;
        if (g2) p2 += step;
    }
    int rank = p + p0 + p1 + p2;

    unsigned ku = (unsigned)(v >> 32);
    float f = (ku & 0x80000000u) ? __uint_as_float(ku ^ 0x80000000u)
                                 : __uint_as_float(~ku);
    ss[head * NN + rank] = f;
    si[head * NN + rank] = (int)(v & 0xffffffffu);
    w0[head * NN + rank] = expf(0.2f * f);
    w1[head * NN + rank] = expf(f);
}

// ============================================================================
// zscan: per (dir, head) block — inclusive prefix scan of w0 (dir 0) or
// inclusive suffix scan of w1 (dir 1), shfl-based, no subtraction in z.
// ============================================================================
__global__ void __launch_bounds__(1024)
zscan_kernel(int layer) {
    const int dir = blockIdx.x, head = blockIdx.y;
    const float* w = (layer == 0) ? (dir == 0 ? g_w0_1 : g_w1_1)
                                  : (dir == 0 ? g_w0_2 : g_w1_2);
    float* z = (layer == 0) ? (dir == 0 ? g_z0_1 : g_z1_1)
                            : (dir == 0 ? g_z0_2 : g_z1_2);

    const int tid = threadIdx.x;
    const int lane = tid & 31, warp = tid >> 5;
    __shared__ float wsum[32], woff[32];

    const int i0 = 4 * tid;
    float4 v = *reinterpret_cast<const float4*>(&w[head * NN + i0]);

    if (dir == 0) {
        float p0 = v.x, p1 = p0 + v.y, p2 = p1 + v.z, p3 = p2 + v.w;
        float x = p3;
#pragma unroll
        for (int o = 1; o < 32; o <<= 1) {
            float y = __shfl_up_sync(0xffffffffu, x, o);
            if (lane >= o) x += y;
        }
        float wexcl = x - p3;
        if (lane == 31) wsum[warp] = x;
        __syncthreads();
        if (warp == 0) {
            float t = wsum[lane];
#pragma unroll
            for (int o = 1; o < 32; o <<= 1) {
                float y = __shfl_up_sync(0xffffffffu, t, o);
                if (lane >= o) t += y;
            }
            woff[lane] = t - wsum[lane];
        }
        __syncthreads();
        float off = woff[warp] + wexcl;
        *reinterpret_cast<float4*>(&z[head * NN + i0]) =
            make_float4(p0 + off, p1 + off, p2 + off, p3 + off);
    } else {
        float q3 = v.w, q2 = q3 + v.z, q1 = q2 + v.y, q0 = q1 + v.x;
        float x = q0;
#pragma unroll
        for (int o = 1; o < 32; o <<= 1) {
            float y = __shfl_down_sync(0xffffffffu, x, o);
            if (lane + o < 32) x += y;
        }
        float wexcl = x - q0;
        if (lane == 0) wsum[warp] = x;
        __syncthreads();
        if (warp == 0) {
            float t = wsum[lane];
#pragma unroll
            for (int o = 1; o < 32; o <<= 1) {
                float y = __shfl_down_sync(0xffffffffu, t, o);
                if (lane + o < 32) t += y;
            }
            woff[lane] = t - wsum[lane];
        }
        __syncthreads();
        float off = woff[warp] + wexcl;
        *reinterpret_cast<float4*>(&z[head * NN + i0]) =
            make_float4(q0 + off, q1 + off, q2 + off, q3 + off);
    }
}

// ============================================================================
// ksearch: grid-wide split points. k = #{ j : ss[j] <= -t }, galloping (exact).
// ============================================================================
__global__ void __launch_bounds__(256)
ksearch_kernel(int layer, int H) {
    const float* t  = (layer == 0) ? g_t1 : g_t2;
    const float* ss = (layer == 0) ? g_ss1 : g_ss2;
    int* kk = (layer == 0) ? g_k1 : g_k2;

    int gid = blockIdx.x * 256 + threadIdx.x;
    if (gid >= H * NN) return;
    int head = gid >> 12;
    const float* ssh = ss + head * NN;
    float tau = -t[gid];
    int pos = 0;
#pragma unroll
    for (int step = NN; step >= 1; step >>= 1) {
        if (pos + step <= NN && __ldg(&ssh[pos + step - 1]) <= tau) pos += step;
    }
    kk[gid] = pos;
}

// ============================================================================
// passA: chunked vector scans of w0*h (prefix) and w1*h (suffix), MLP=16 gathers
// ============================================================================
__global__ void __launch_bounds__(CD)
passA_kernel(int layer, int F) {
    const float* h  = (layer == 0) ? g_h1 : g_h2;
    const int*   si = (layer == 0) ? g_si1 : g_si2;
    const float* w0 = (layer == 0) ? g_w0_1 : g_w0_2;
    const float* w1 = (layer == 0) ? g_w1_1 : g_w1_2;
    float* I0 = (layer == 0) ? g_I0_1 : g_I0_2;
    float* S1 = (layer == 0) ? g_S1_1 : g_S1_2;

    const int chunk = blockIdx.x, head = blockIdx.y, dir = blockIdx.z;
    const int c = threadIdx.x;
    const int base = head * NN + chunk * CHUNK;

    __shared__ int   sj[CHUNK];
    __shared__ float sw[CHUNK];
    const float* wsel = (dir == 0) ? w0 : w1;
    for (int r = threadIdx.x; r < CHUNK; r += blockDim.x) {
        sj[r] = si[base + r] * F + head * CD;
        sw[r] = wsel[base + r];
    }
    __syncthreads();

    float acc = 0.f;
    if (dir == 0) {
        float* dst = I0 + (size_t)base * CD + c;
        for (int rr = 0; rr < CHUNK; rr += 16) {
            float v[16];
#pragma unroll
            for (int u = 0; u < 16; u++) v[u] = __ldg(&h[sj[rr + u] + c]);
#pragma unroll
            for (int u = 0; u < 16; u++) {
                acc = fmaf(sw[rr + u], v[u], acc);
                dst[(size_t)(rr + u) * CD] = acc;
            }
        }
    } else {
        float* dst = S1 + (size_t)base * CD + c;
        for (int rr = CHUNK - 16; rr >= 0; rr -= 16) {
            float v[16];
#pragma unroll
            for (int u = 15; u >= 0; u--) v[u] = __ldg(&h[sj[rr + u] + c]);
#pragma unroll
            for (int u = 15; u >= 0; u--) {
                acc = fmaf(sw[rr + u], v[u], acc);
                dst[(size_t)(rr + u) * CD] = acc;
            }
        }
    }
}

// ---------------- cross-chunk offsets ----------------
__global__ void passB_kernel(int layer) {
    const float* I0 = (layer == 0) ? g_I0_1 : g_I0_2;
    const float* S1 = (layer == 0) ? g_S1_1 : g_S1_2;
    float* O0 = (layer == 0) ? g_O0_1 : g_O0_2;
    float* O1 = (layer == 0) ? g_O1_1 : g_O1_2;

    int head = blockIdx.x, c = threadIdx.x;
    float acc = 0.f;
    for (int ch = 0; ch < NCH; ch++) {
        O0[(head * NCH + ch) * CD + c] = acc;
        acc += I0[(head * NN + ch * CHUNK + CHUNK - 1) * CD + c];
    }
    acc = 0.f;
    for (int ch = NCH - 1; ch >= 0; ch--) {
        O1[(head * NCH + ch) * CD + c] = acc;
        acc += S1[(head * NN + ch * CHUNK) * CD + c];
    }
}

// ---------------- per-dest lookup: 2 table reads -> out + bias + elu ----------------
__global__ void __launch_bounds__(CD)
lookup_kernel(int layer, const float* __restrict__ bias, int F) {
    const float* t  = (layer == 0) ? g_t1 : g_t2;
    const int*   kk = (layer == 0) ? g_k1 : g_k2;
    const float* I0 = (layer == 0) ? g_I0_1 : g_I0_2;
    const float* S1 = (layer == 0) ? g_S1_1 : g_S1_2;
    const float* O0 = (layer == 0) ? g_O0_1 : g_O0_2;
    const float* O1 = (layer == 0) ? g_O1_1 : g_O1_2;
    const float* z0 = (layer == 0) ? g_z0_1 : g_z0_2;
    const float* z1 = (layer == 0) ? g_z1_1 : g_z1_2;
    float* xout = (layer == 0) ? g_x1 : g_x2;

    int head = blockIdx.y, c = threadIdx.x;
    float bv = bias[head * CD + c];

#pragma unroll 2
    for (int u = 0; u < 8; u++) {
        int i = blockIdx.x * 8 + u;
        float tv = t[head * NN + i];
        int k = kk[head * NN + i];

        float A0 = 0.f, z0v = 0.f, A1 = 0.f, z1v = 0.f;
        if (k > 0) {
            A0 = I0[(size_t)(head * NN + k - 1) * CD + c] +
                 O0[(head * NCH + (k - 1) / CHUNK) * CD + c];
            z0v = z0[head * NN + k - 1];
        }
        if (k < NN) {
            A1 = S1[(size_t)(head * NN + k) * CD + c] +
                 O1[(head * NCH + k / CHUNK) * CD + c];
            z1v = z1[head * NN + k];
        }
        float et  = expf(tv);
        float et2 = expf(0.2f * tv);
        float num = et * A1 + et2 * A0;
        float den = et * z1v + et2 * z0v;
        float o = num / den + bv;
        xout[i * F + head * CD + c] = elu1(o);
    }
}

// ---------------- column mean over nodes + FC (fused final) ----------------
__global__ void colpart_kernel() {
    int b = blockIdx.x, c = threadIdx.x;
    float acc = 0.f;
    for (int r = 0; r < NN / 32; r++) acc += g_x2[(b * (NN / 32) + r) * CD + c];
    g_part[b * CD + c] = acc;
}
__global__ void __launch_bounds__(DIN)
colfinal_fc_kernel(const float* __restrict__ fcW, const float* __restrict__ fcb,
                   float* __restrict__ out) {
    __shared__ float m[CD];
    int tid = threadIdx.x;
    if (tid < CD) {
        float a = 0.f;
        for (int b = 0; b < 32; b++) a += g_part[b * CD + tid];
        m[tid] = a * (1.f / (float)NN);
    }
    __syncthreads();
    if (tid < DIN) {
        float acc = fcb[tid];
#pragma unroll 8
        for (int c = 0; c < CD; c++) acc = fmaf(m[c], fcW[c * DIN + tid], acc);
        out[tid] = acc;
    }
}

// ---------------- launch ----------------
extern "C" void kernel_launch(void* const* d_in, const int* in_sizes, int n_in,
                              void* d_out, int out_size) {
    const float* X   = (const float*)d_in[0];
    const float* W1  = (const float*)d_in[1];
    const float* as1 = (const float*)d_in[2];
    const float* ad1 = (const float*)d_in[3];
    const float* b1  = (const float*)d_in[4];
    const float* W2  = (const float*)d_in[5];
    const float* as2 = (const float*)d_in[6];
    const float* ad2 = (const float*)d_in[7];
    const float* b2  = (const float*)d_in[8];
    const float* fcW = (const float*)d_in[9];
    const float* fcb = (const float*)d_in[10];
    float* out = (float*)d_out;

    // Layer 1: M=4096, K=768, N=512 (BM=128, grid 32x4)
    gemm_st_kernel<8><<<dim3(NN / 128, F1 / 128), 256>>>(X, W1, as1, ad1, 0, NN, F1, DIN);
    sortchunk_kernel<<<dim3(NSC, HH1), 256>>>(0);
    merge_kernel<<<(HH1 * NN) / 256, 256>>>(0, HH1);
    zscan_kernel<<<dim3(2, HH1), 1024>>>(0);
    ksearch_kernel<<<(HH1 * NN) / 256, 256>>>(0, HH1);
    passA_kernel<<<dim3(NCH, HH1, 2), CD>>>(0, F1);
    passB_kernel<<<HH1, CD>>>(0);
    lookup_kernel<<<dim3(NN / 8, HH1), CD>>>(0, b1, F1);

    // Layer 2: M=4096, K=512, N=128 (BM=32, grid 128x1)
    gemm_st_kernel<2><<<dim3(NN / 32, 1), 256>>>(nullptr, W2, as2, ad2, 1, NN, CD, F1);
    sortchunk_kernel<<<dim3(NSC, 1), 256>>>(1);
    merge_kernel<<<NN / 256, 256>>>(1, 1);
    zscan_kernel<<<dim3(2, 1), 1024>>>(1);
    ksearch_kernel<<<NN / 256, 256>>>(1, 1);
    passA_kernel<<<dim3(NCH, 1, 2), CD>>>(1, CD);
    passB_kernel<<<1, CD>>>(1);
    lookup_kernel<<<dim3(NN / 8, 1), CD>>>(1, b2, CD);

    // Mean + FC
    colpart_kernel<<<32, CD>>>();
    colfinal_fc_kernel<<<1, DIN>>>(fcW, fcb, out);
}

// round 9
// speedup vs baseline: 2.0026x; 1.0149x over previous
#include <cuda_runtime.h>
#include <math.h>

#define NN    4096
#define DIN   768
#define CD    128
#define HH1   4
#define F1    512
#define CHUNK 256
#define NCH   (NN/CHUNK)   // 16 (passA chunks)
#define SC    1024         // sort chunk size
#define NSC   4            // sort chunks

typedef unsigned long long ull;

// ---------------- device scratch (no allocs allowed) ----------------
__device__ float g_h1[NN*F1];
__device__ float g_x1[NN*F1];
__device__ float g_h2[NN*CD];
__device__ float g_x2[NN*CD];

__device__ float g_s1[HH1*NN], g_t1[HH1*NN], g_ss1[HH1*NN];
__device__ float g_w0_1[HH1*NN], g_w1_1[HH1*NN], g_z0_1[HH1*NN], g_z1_1[HH1*NN];
__device__ int   g_si1[HH1*NN];
__device__ int   g_k1[HH1*NN];
__device__ float2 g_a1[HH1*NN];
__device__ float g_I0_1[HH1*NN*CD], g_S1_1[HH1*NN*CD];
__device__ float g_O0_1[HH1*NCH*CD], g_O1_1[HH1*NCH*CD];

__device__ float g_s2[NN], g_t2[NN], g_ss2[NN];
__device__ float g_w0_2[NN], g_w1_2[NN], g_z0_2[NN], g_z1_2[NN];
__device__ int   g_si2[NN];
__device__ int   g_k2[NN];
__device__ float2 g_a2[NN];
__device__ float g_I0_2[NN*CD], g_S1_2[NN*CD];
__device__ float g_O0_2[NCH*CD], g_O1_2[NCH*CD];

__device__ ull   g_sc[HH1*NN];   // sorted chunks (reused by both layers)

__device__ float g_part[32*CD];

// ---------------- f32x2 helpers (FFMA2 via PTX) ----------------
__device__ __forceinline__ ull fma2(ull a, ull b, ull c) {
    ull d;
    asm("fma.rn.f32x2 %0, %1, %2, %3;" : "=l"(d) : "l"(a), "l"(b), "l"(c));
    return d;
}
__device__ __forceinline__ ull pack2(float x, float y) {
    ull d;
    unsigned xi = __float_as_uint(x), yi = __float_as_uint(y);
    asm("mov.b64 %0, {%1, %2};" : "=l"(d) : "r"(xi), "r"(yi));
    return d;
}
__device__ __forceinline__ void unpack2(ull d, float& x, float& y) {
    unsigned lo, hi;
    asm("mov.b64 {%0, %1}, %2;" : "=r"(lo), "=r"(hi) : "l"(d));
    x = __uint_as_float(lo); y = __uint_as_float(hi);
}
__device__ __forceinline__ float elu1(float x) { return x > 0.f ? x : expm1f(x); }

// ============================================================================
// GEMM + fused s/t epilogue. 256 threads, 2 warps/SMSP.
// C[M,N] = A[M,K]*B[K,N]; BN=128 (==CD) so blockIdx.y==head.
// Thread grid 16(m)x16(n); thread tile TM x 8; BK=16; double-buffered smem.
// BM = 16*TM. s/t dots reduced via shfl (16-lane halves).
// ============================================================================
template<int TM>
__global__ void __launch_bounds__(256)
gemm_st_kernel(const float* __restrict__ Aext, const float* __restrict__ B,
               const float* __restrict__ asrc, const float* __restrict__ adst,
               int layer, int M, int N, int K) {
    constexpr int BN = 128, BK = 16;
    constexpr int BM = 16 * TM;
    constexpr int ASTRIDE = BM + 4;            // pad keeps 16B alignment (BM mult of 16)
    constexpr int NA = (BM * 4 + 255) / 256;   // A float4 loads per thread
    const float* A = (layer == 0) ? Aext : g_x1;
    float* C  = (layer == 0) ? g_h1 : g_h2;
    float* gs = (layer == 0) ? g_s1 : g_s2;
    float* gt = (layer == 0) ? g_t1 : g_t2;

    __shared__ __align__(16) float As[2][BK][ASTRIDE];
    __shared__ __align__(16) float Bs[2][BK][BN];

    const int tid = threadIdx.x;
    const int bm = blockIdx.x * BM, bn = blockIdx.y * BN;
    const int head = blockIdx.y;
    const int nt = tid & 15, mt = tid >> 4;
    const int m0 = mt * TM;

    ull acc[TM][4];
#pragma unroll
    for (int i = 0; i < TM; i++)
#pragma unroll
        for (int u = 0; u < 4; u++) acc[i][u] = 0ull;

    float4 apre[NA], bpre[2];

    // prefetch tile 0
#pragma unroll
    for (int j = 0; j < NA; j++) {
        int idx = tid + j * 256;
        if (idx < BM * 4) {
            int row = idx >> 2, c4 = idx & 3;
            apre[j] = *reinterpret_cast<const float4*>(&A[(bm + row) * K + c4 * 4]);
        }
    }
#pragma unroll
    for (int j = 0; j < 2; j++) {
        int idx = tid + j * 256;
        int row = idx >> 5, c4 = idx & 31;
        bpre[j] = *reinterpret_cast<const float4*>(&B[row * N + bn + c4 * 4]);
    }
    // store tile 0
#pragma unroll
    for (int j = 0; j < NA; j++) {
        int idx = tid + j * 256;
        if (idx < BM * 4) {
            int row = idx >> 2, c4 = idx & 3;
#pragma unroll
            for (int w = 0; w < 4; w++) As[0][c4 * 4 + w][row] = (&apre[j].x)[w];
        }
    }
#pragma unroll
    for (int j = 0; j < 2; j++) {
        int idx = tid + j * 256;
        int row = idx >> 5, c4 = idx & 31;
        *reinterpret_cast<float4*>(&Bs[0][row][c4 * 4]) = bpre[j];
    }
    __syncthreads();

    const int ktiles = K / BK;
    for (int t = 0; t < ktiles; t++) {
        const int cur = t & 1;
        if (t + 1 < ktiles) {
            const int k0 = (t + 1) * BK;
#pragma unroll
            for (int j = 0; j < NA; j++) {
                int idx = tid + j * 256;
                if (idx < BM * 4) {
                    int row = idx >> 2, c4 = idx & 3;
                    apre[j] = *reinterpret_cast<const float4*>(&A[(bm + row) * K + k0 + c4 * 4]);
                }
            }
#pragma unroll
            for (int j = 0; j < 2; j++) {
                int idx = tid + j * 256;
                int row = idx >> 5, c4 = idx & 31;
                bpre[j] = *reinterpret_cast<const float4*>(&B[(k0 + row) * N + bn + c4 * 4]);
            }
        }
#pragma unroll
        for (int kk = 0; kk < BK; kk++) {
            float a[TM];
            if (TM == 8) {
                float4 t0 = *reinterpret_cast<const float4*>(&As[cur][kk][m0]);
                float4 t1 = *reinterpret_cast<const float4*>(&As[cur][kk][m0 + 4]);
                a[0]=t0.x; a[1]=t0.y; a[2]=t0.z; a[3]=t0.w;
                a[4]=t1.x; a[5]=t1.y; a[6]=t1.z; a[7]=t1.w;
            } else if (TM == 4) {
                float4 t0 = *reinterpret_cast<const float4*>(&As[cur][kk][m0]);
                a[0]=t0.x; a[1]=t0.y; a[2]=t0.z; a[3]=t0.w;
            } else {
                float2 t0 = *reinterpret_cast<const float2*>(&As[cur][kk][m0]);
                a[0]=t0.x; a[1]=t0.y;
            }
            ulonglong2 bb0 = *reinterpret_cast<const ulonglong2*>(&Bs[cur][kk][nt * 8]);
            ulonglong2 bb1 = *reinterpret_cast<const ulonglong2*>(&Bs[cur][kk][nt * 8 + 4]);
#pragma unroll
            for (int i = 0; i < TM; i++) {
                ull a2 = pack2(a[i], a[i]);
                acc[i][0] = fma2(a2, bb0.x, acc[i][0]);
                acc[i][1] = fma2(a2, bb0.y, acc[i][1]);
                acc[i][2] = fma2(a2, bb1.x, acc[i][2]);
                acc[i][3] = fma2(a2, bb1.y, acc[i][3]);
            }
        }
        if (t + 1 < ktiles) {
            const int nxt = cur ^ 1;
#pragma unroll
            for (int j = 0; j < NA; j++) {
                int idx = tid + j * 256;
                if (idx < BM * 4) {
                    int row = idx >> 2, c4 = idx & 3;
#pragma unroll
                    for (int w = 0; w < 4; w++) As[nxt][c4 * 4 + w][row] = (&apre[j].x)[w];
                }
            }
#pragma unroll
            for (int j = 0; j < 2; j++) {
                int idx = tid + j * 256;
                int row = idx >> 5, c4 = idx & 31;
                *reinterpret_cast<float4*>(&Bs[nxt][row][c4 * 4]) = bpre[j];
            }
        }
        __syncthreads();
    }

    // epilogue: store C + fused s/t dots (shfl-reduced over 16 n-threads)
    float4 asv0 = *reinterpret_cast<const float4*>(&asrc[head * CD + nt * 8]);
    float4 asv1 = *reinterpret_cast<const float4*>(&asrc[head * CD + nt * 8 + 4]);
    float4 adv0 = *reinterpret_cast<const float4*>(&adst[head * CD + nt * 8]);
    float4 adv1 = *reinterpret_cast<const float4*>(&adst[head * CD + nt * 8 + 4]);

#pragma unroll
    for (int i = 0; i < TM; i++) {
        float x0, x1, x2, x3, x4, x5, x6, x7;
        unpack2(acc[i][0], x0, x1);
        unpack2(acc[i][1], x2, x3);
        unpack2(acc[i][2], x4, x5);
        unpack2(acc[i][3], x6, x7);
        *reinterpret_cast<float4*>(&C[(bm + m0 + i) * N + bn + nt * 8]) =
            make_float4(x0, x1, x2, x3);
        *reinterpret_cast<float4*>(&C[(bm + m0 + i) * N + bn + nt * 8 + 4]) =
            make_float4(x4, x5, x6, x7);
        float sp = x0*asv0.x + x1*asv0.y + x2*asv0.z + x3*asv0.w
                 + x4*asv1.x + x5*asv1.y + x6*asv1.z + x7*asv1.w;
        float tp = x0*adv0.x + x1*adv0.y + x2*adv0.z + x3*adv0.w
                 + x4*adv1.x + x5*adv1.y + x6*adv1.z + x7*adv1.w;
#pragma unroll
        for (int o = 1; o < 16; o <<= 1) {
            sp += __shfl_xor_sync(0xffffffffu, sp, o);
            tp += __shfl_xor_sync(0xffffffffu, tp, o);
        }
        if (nt == 0) {
            gs[head * NN + bm + m0 + i] = sp;
            gt[head * NN + bm + m0 + i] = tp;
        }
    }
}

// ============================================================================
// Sort stage 1: bitonic sort of 1024-element chunks (key=transformed s, val=idx)
// ============================================================================
__device__ __forceinline__ void cswap(ull& a, ull& b, bool asc) {
    if ((a > b) == asc) { ull t = a; a = b; b = t; }
}

__global__ void __launch_bounds__(256)
sortchunk_kernel(int layer) {
    const float* s = (layer == 0) ? g_s1 : g_s2;
    const int head = blockIdx.y, chunk = blockIdx.x;
    const int tid = threadIdx.x;
    __shared__ ull kv[SC];

    const int gbase = head * NN + chunk * SC;
#pragma unroll
    for (int e = 0; e < 4; e++) {
        int i = tid + e * 256;
        unsigned u = __float_as_uint(s[gbase + i]);
        u = (u & 0x80000000u) ? ~u : (u | 0x80000000u);
        kv[i] = ((ull)u << 32) | (unsigned)(chunk * SC + i);
    }
    __syncthreads();

    {
        int i0 = 4 * tid;
        ull v0 = kv[i0], v1 = kv[i0 + 1], v2 = kv[i0 + 2], v3 = kv[i0 + 3];
        cswap(v0, v1, true); cswap(v2, v3, false);
        bool asc = ((i0 & 4) == 0);
        cswap(v0, v2, asc); cswap(v1, v3, asc);
        cswap(v0, v1, asc); cswap(v2, v3, asc);
        kv[i0] = v0; kv[i0 + 1] = v1; kv[i0 + 2] = v2; kv[i0 + 3] = v3;
    }
    __syncthreads();

    for (int k = 8; k <= SC; k <<= 1) {
        for (int j = k >> 1; j >= 4; j >>= 1) {
#pragma unroll
            for (int e = 0; e < 4; e++) {
                int i = tid + e * 256;
                if ((i & j) == 0) {
                    int p = i | j;
                    ull a = kv[i], b = kv[p];
                    bool asc = ((i & k) == 0);
                    if ((a > b) == asc) { kv[i] = b; kv[p] = a; }
                }
            }
            __syncthreads();
        }
        {
            int i0 = 4 * tid;
            ull v0 = kv[i0], v1 = kv[i0 + 1], v2 = kv[i0 + 2], v3 = kv[i0 + 3];
            bool asc = ((i0 & k) == 0);
            cswap(v0, v2, asc); cswap(v1, v3, asc);
            cswap(v0, v1, asc); cswap(v2, v3, asc);
            kv[i0] = v0; kv[i0 + 1] = v1; kv[i0 + 2] = v2; kv[i0 + 3] = v3;
        }
        __syncthreads();
    }

#pragma unroll
    for (int e = 0; e < 4; e++) {
        int i = tid + e * 256;
        g_sc[(head * NSC + chunk) * SC + i] = kv[i];
    }
}

// ============================================================================
// Sort stage 2: rank-merge of 4 sorted chunks (galloping lower bound, exact)
// + fused weight computation w0=exp(0.2 s), w1=exp(s).
// ============================================================================
__global__ void __launch_bounds__(256)
merge_kernel(int layer, int H) {
    float* ss = (layer == 0) ? g_ss1 : g_ss2;
    int*   si = (layer == 0) ? g_si1 : g_si2;
    float* w0 = (layer == 0) ? g_w0_1 : g_w0_2;
    float* w1 = (layer == 0) ? g_w1_1 : g_w1_2;

    int gid = blockIdx.x * 256 + threadIdx.x;
    if (gid >= H * NN) return;
    int head = gid >> 12;
    int i = gid & (NN - 1);
    int c = i >> 10, p = i & (SC - 1);

    const ull* base = g_sc + (size_t)head * NN;
    ull v = base[c * SC + p];

    const ull* oth[3];
    int cc = 0;
#pragma unroll
    for (int q = 0; q < 4; q++) if (q != c) oth[cc++] = base + q * SC;

    int p0 = 0, p1 = 0, p2 = 0;
#pragma unroll
    for (int step = SC; step >= 1; step >>= 1) {
        bool g0 = (p0 + step <= SC) && (__ldg(&oth[0][p0 + step - 1]) < v);
        bool g1 = (p1 + step <= SC) && (__ldg(&oth[1][p1 + step - 1]) < v);
        bool g2 = (p2 + step <= SC) && (__ldg(&oth[2][p2 + step - 1]) < v);
        if (g0) p0 += step;
        if (g1) p1 += step;
        if (g2) p2 += step;
    }
    int rank = p + p0 + p1 + p2;

    unsigned ku = (unsigned)(v >> 32);
    float f = (ku & 0x80000000u) ? __uint_as_float(ku ^ 0x80000000u)
                                 : __uint_as_float(~ku);
    ss[head * NN + rank] = f;
    si[head * NN + rank] = (int)(v & 0xffffffffu);
    w0[head * NN + rank] = expf(0.2f * f);
    w1[head * NN + rank] = expf(f);
}

// ============================================================================
// zscan: per (dir, head) block — inclusive prefix scan of w0 (dir 0) or
// inclusive suffix scan of w1 (dir 1), shfl-based, no subtraction in z.
// ============================================================================
__global__ void __launch_bounds__(1024)
zscan_kernel(int layer) {
    const int dir = blockIdx.x, head = blockIdx.y;
    const float* w = (layer == 0) ? (dir == 0 ? g_w0_1 : g_w1_1)
                                  : (dir == 0 ? g_w0_2 : g_w1_2);
    float* z = (layer == 0) ? (dir == 0 ? g_z0_1 : g_z1_1)
                            : (dir == 0 ? g_z0_2 : g_z1_2);

    const int tid = threadIdx.x;
    const int lane = tid & 31, warp = tid >> 5;
    __shared__ float wsum[32], woff[32];

    const int i0 = 4 * tid;
    float4 v = *reinterpret_cast<const float4*>(&w[head * NN + i0]);

    if (dir == 0) {
        float p0 = v.x, p1 = p0 + v.y, p2 = p1 + v.z, p3 = p2 + v.w;
        float x = p3;
#pragma unroll
        for (int o = 1; o < 32; o <<= 1) {
            float y = __shfl_up_sync(0xffffffffu, x, o);
            if (lane >= o) x += y;
        }
        float wexcl = x - p3;
        if (lane == 31) wsum[warp] = x;
        __syncthreads();
        if (warp == 0) {
            float t = wsum[lane];
#pragma unroll
            for (int o = 1; o < 32; o <<= 1) {
                float y = __shfl_up_sync(0xffffffffu, t, o);
                if (lane >= o) t += y;
            }
            woff[lane] = t - wsum[lane];
        }
        __syncthreads();
        float off = woff[warp] + wexcl;
        *reinterpret_cast<float4*>(&z[head * NN + i0]) =
            make_float4(p0 + off, p1 + off, p2 + off, p3 + off);
    } else {
        float q3 = v.w, q2 = q3 + v.z, q1 = q2 + v.y, q0 = q1 + v.x;
        float x = q0;
#pragma unroll
        for (int o = 1; o < 32; o <<= 1) {
            float y = __shfl_down_sync(0xffffffffu, x, o);
            if (lane + o < 32) x += y;
        }
        float wexcl = x - q0;
        if (lane == 0) wsum[warp] = x;
        __syncthreads();
        if (warp == 0) {
            float t = wsum[lane];
#pragma unroll
            for (int o = 1; o < 32; o <<= 1) {
                float y = __shfl_down_sync(0xffffffffu, t, o);
                if (lane + o < 32) t += y;
            }
            woff[lane] = t - wsum[lane];
        }
        __syncthreads();
        float off = woff[warp] + wexcl;
        *reinterpret_cast<float4*>(&z[head * NN + i0]) =
            make_float4(q0 + off, q1 + off, q2 + off, q3 + off);
    }
}

// ============================================================================
// ksearch: grid-wide split points + per-(head,node) scalar coefficients.
// k = #{ j : ss[j] <= -t } (galloping, exact); then
// den = e^t*z1[k] + e^{0.2t}*z0[k-1];  a1 = [k<NN] e^t/den;  a0 = [k>0] e^{0.2t}/den.
// lookup's per-channel work becomes 2 FMA (no MUFU / no divide).
// ============================================================================
__global__ void __launch_bounds__(256)
ksearch_kernel(int layer, int H) {
    const float* t  = (layer == 0) ? g_t1 : g_t2;
    const float* ss = (layer == 0) ? g_ss1 : g_ss2;
    const float* z0 = (layer == 0) ? g_z0_1 : g_z0_2;
    const float* z1 = (layer == 0) ? g_z1_1 : g_z1_2;
    int*    kk = (layer == 0) ? g_k1 : g_k2;
    float2* aa = (layer == 0) ? g_a1 : g_a2;

    int gid = blockIdx.x * 256 + threadIdx.x;
    if (gid >= H * NN) return;
    int head = gid >> 12;
    const float* ssh = ss + head * NN;
    float tv = t[gid];
    float tau = -tv;
    int pos = 0;
#pragma unroll
    for (int step = NN; step >= 1; step >>= 1) {
        if (pos + step <= NN && __ldg(&ssh[pos + step - 1]) <= tau) pos += step;
    }
    kk[gid] = pos;

    float z0v = (pos > 0)  ? z0[head * NN + pos - 1] : 0.f;
    float z1v = (pos < NN) ? z1[head * NN + pos]     : 0.f;
    float et  = expf(tv);
    float et2 = expf(0.2f * tv);
    float inv = 1.f / (et * z1v + et2 * z0v);
    float a0 = (pos > 0)  ? et2 * inv : 0.f;
    float a1 = (pos < NN) ? et  * inv : 0.f;
    aa[gid] = make_float2(a0, a1);
}

// ============================================================================
// passA: chunked vector scans of w0*h (prefix) and w1*h (suffix), MLP=16 gathers
// ============================================================================
__global__ void __launch_bounds__(CD)
passA_kernel(int layer, int F) {
    const float* h  = (layer == 0) ? g_h1 : g_h2;
    const int*   si = (layer == 0) ? g_si1 : g_si2;
    const float* w0 = (layer == 0) ? g_w0_1 : g_w0_2;
    const float* w1 = (layer == 0) ? g_w1_1 : g_w1_2;
    float* I0 = (layer == 0) ? g_I0_1 : g_I0_2;
    float* S1 = (layer == 0) ? g_S1_1 : g_S1_2;

    const int chunk = blockIdx.x, head = blockIdx.y, dir = blockIdx.z;
    const int c = threadIdx.x;
    const int base = head * NN + chunk * CHUNK;

    __shared__ int   sj[CHUNK];
    __shared__ float sw[CHUNK];
    const float* wsel = (dir == 0) ? w0 : w1;
    for (int r = threadIdx.x; r < CHUNK; r += blockDim.x) {
        sj[r] = si[base + r] * F + head * CD;
        sw[r] = wsel[base + r];
    }
    __syncthreads();

    float acc = 0.f;
    if (dir == 0) {
        float* dst = I0 + (size_t)base * CD + c;
        for (int rr = 0; rr < CHUNK; rr += 16) {
            float v[16];
#pragma unroll
            for (int u = 0; u < 16; u++) v[u] = __ldg(&h[sj[rr + u] + c]);
#pragma unroll
            for (int u = 0; u < 16; u++) {
                acc = fmaf(sw[rr + u], v[u], acc);
                dst[(size_t)(rr + u) * CD] = acc;
            }
        }
    } else {
        float* dst = S1 + (size_t)base * CD + c;
        for (int rr = CHUNK - 16; rr >= 0; rr -= 16) {
            float v[16];
#pragma unroll
            for (int u = 15; u >= 0; u--) v[u] = __ldg(&h[sj[rr + u] + c]);
#pragma unroll
            for (int u = 15; u >= 0; u--) {
                acc = fmaf(sw[rr + u], v[u], acc);
                dst[(size_t)(rr + u) * CD] = acc;
            }
        }
    }
}

// ---------------- cross-chunk offsets ----------------
__global__ void passB_kernel(int layer) {
    const float* I0 = (layer == 0) ? g_I0_1 : g_I0_2;
    const float* S1 = (layer == 0) ? g_S1_1 : g_S1_2;
    float* O0 = (layer == 0) ? g_O0_1 : g_O0_2;
    float* O1 = (layer == 0) ? g_O1_1 : g_O1_2;

    int head = blockIdx.x, c = threadIdx.x;
    float acc = 0.f;
    for (int ch = 0; ch < NCH; ch++) {
        O0[(head * NCH + ch) * CD + c] = acc;
        acc += I0[(head * NN + ch * CHUNK + CHUNK - 1) * CD + c];
    }
    acc = 0.f;
    for (int ch = NCH - 1; ch >= 0; ch--) {
        O1[(head * NCH + ch) * CD + c] = acc;
        acc += S1[(head * NN + ch * CHUNK) * CD + c];
    }
}

// ---------------- per-dest lookup: 2 clamped table reads + 2 FMA + elu -----------
__global__ void __launch_bounds__(CD)
lookup_kernel(int layer, const float* __restrict__ bias, int F) {
    const int*    kk = (layer == 0) ? g_k1 : g_k2;
    const float2* aa = (layer == 0) ? g_a1 : g_a2;
    const float* I0 = (layer == 0) ? g_I0_1 : g_I0_2;
    const float* S1 = (layer == 0) ? g_S1_1 : g_S1_2;
    const float* O0 = (layer == 0) ? g_O0_1 : g_O0_2;
    const float* O1 = (layer == 0) ? g_O1_1 : g_O1_2;
    float* xout = (layer == 0) ? g_x1 : g_x2;

    int head = blockIdx.y, c = threadIdx.x;
    float bv = bias[head * CD + c];

#pragma unroll 2
    for (int u = 0; u < 8; u++) {
        int i = blockIdx.x * 8 + u;
        int k = kk[head * NN + i];
        float2 a = aa[head * NN + i];

        int k0i = (k > 0) ? (k - 1) : 0;
        int k1i = (k < NN) ? k : (NN - 1);
        float A0 = I0[(size_t)(head * NN + k0i) * CD + c] +
                   O0[(head * NCH + k0i / CHUNK) * CD + c];
        float A1 = S1[(size_t)(head * NN + k1i) * CD + c] +
                   O1[(head * NCH + k1i / CHUNK) * CD + c];
        float o = fmaf(a.y, A1, fmaf(a.x, A0, bv));
        xout[i * F + head * CD + c] = elu1(o);
    }
}

// ---------------- column mean over nodes + FC (fused final) ----------------
__global__ void colpart_kernel() {
    int b = blockIdx.x, c = threadIdx.x;
    float acc = 0.f;
    for (int r = 0; r < NN / 32; r++) acc += g_x2[(b * (NN / 32) + r) * CD + c];
    g_part[b * CD + c] = acc;
}
__global__ void __launch_bounds__(DIN)
colfinal_fc_kernel(const float* __restrict__ fcW, const float* __restrict__ fcb,
                   float* __restrict__ out) {
    __shared__ float m[CD];
    int tid = threadIdx.x;
    if (tid < CD) {
        float a = 0.f;
        for (int b = 0; b < 32; b++) a += g_part[b * CD + tid];
        m[tid] = a * (1.f / (float)NN);
    }
    __syncthreads();
    if (tid < DIN) {
        float acc = fcb[tid];
#pragma unroll 8
        for (int c = 0; c < CD; c++) acc = fmaf(m[c], fcW[c * DIN + tid], acc);
        out[tid] = acc;
    }
}

// ---------------- launch ----------------
extern "C" void kernel_launch(void* const* d_in, const int* in_sizes, int n_in,
                              void* d_out, int out_size) {
    const float* X   = (const float*)d_in[0];
    const float* W1  = (const float*)d_in[1];
    const float* as1 = (const float*)d_in[2];
    const float* ad1 = (const float*)d_in[3];
    const float* b1  = (const float*)d_in[4];
    const float* W2  = (const float*)d_in[5];
    const float* as2 = (const float*)d_in[6];
    const float* ad2 = (const float*)d_in[7];
    const float* b2  = (const float*)d_in[8];
    const float* fcW = (const float*)d_in[9];
    const float* fcb = (const float*)d_in[10];
    float* out = (float*)d_out;

    // Layer 1: M=4096, K=768, N=512 (BM=128, grid 32x4)
    gemm_st_kernel<8><<<dim3(NN / 128, F1 / 128), 256>>>(X, W1, as1, ad1, 0, NN, F1, DIN);
    sortchunk_kernel<<<dim3(NSC, HH1), 256>>>(0);
    merge_kernel<<<(HH1 * NN) / 256, 256>>>(0, HH1);
    zscan_kernel<<<dim3(2, HH1), 1024>>>(0);
    ksearch_kernel<<<(HH1 * NN) / 256, 256>>>(0, HH1);
    passA_kernel<<<dim3(NCH, HH1, 2), CD>>>(0, F1);
    passB_kernel<<<HH1, CD>>>(0);
    lookup_kernel<<<dim3(NN / 8, HH1), CD>>>(0, b1, F1);

    // Layer 2: M=4096, K=512, N=128 (BM=32, grid 128x1)
    gemm_st_kernel<2><<<dim3(NN / 32, 1), 256>>>(nullptr, W2, as2, ad2, 1, NN, CD, F1);
    sortchunk_kernel<<<dim3(NSC, 1), 256>>>(1);
    merge_kernel<<<NN / 256, 256>>>(1, 1);
    zscan_kernel<<<dim3(2, 1), 1024>>>(1);
    ksearch_kernel<<<NN / 256, 256>>>(1, 1);
    passA_kernel<<<dim3(NCH, 1, 2), CD>>>(1, CD);
    passB_kernel<<<1, CD>>>(1);
    lookup_kernel<<<dim3(NN / 8, 1), CD>>>(1, b2, CD);

    // Mean + FC
    colpart_kernel<<<32, CD>>>();
    colfinal_fc_kernel<<<1, DIN>>>(fcW, fcb, out);
}

// round 12
// speedup vs baseline: 2.2877x; 1.1424x over previous
#include <cuda_runtime.h>
#include <cuda_bf16.h>
#include <stdint.h>
#include <math.h>

#define NN    4096
#define DIN   768
#define CD    128
#define HH1   4
#define F1    512
#define CHUNK 256
#define NCH   (NN/CHUNK)   // 16 (passA chunks)
#define SC    1024         // sort chunk size
#define NSC   4            // sort chunks
#define BK1   32           // gemm1 K-chunk
#define NCH1  (DIN/BK1)    // 24
#define TSTR  40           // smem row stride in bf16 elems (80B) -> conflict-free frags
#define TILEB (128*TSTR*2) // 10240 B per tile

typedef unsigned long long ull;

// ---------------- device scratch (no allocs allowed) ----------------
__device__ float g_h1[NN*F1];
__device__ float g_x1[NN*F1];
__device__ float g_h2[NN*CD];
__device__ float g_x2[NN*CD];

__device__ __nv_bfloat16 g_XH[NN*DIN], g_XL[NN*DIN];      // split X
__device__ __nv_bfloat16 g_BtH[F1*DIN], g_BtL[F1*DIN];    // split W1^T [512][768]

__device__ float g_s1[HH1*NN], g_t1[HH1*NN], g_ss1[HH1*NN];
__device__ float g_w0_1[HH1*NN], g_w1_1[HH1*NN], g_z0_1[HH1*NN], g_z1_1[HH1*NN];
__device__ int   g_si1[HH1*NN];
__device__ int   g_k1[HH1*NN];
__device__ float2 g_a1[HH1*NN];
__device__ float g_I0_1[HH1*NN*CD], g_S1_1[HH1*NN*CD];
__device__ float g_O0_1[HH1*NCH*CD], g_O1_1[HH1*NCH*CD];

__device__ float g_s2[NN], g_t2[NN], g_ss2[NN];
__device__ float g_w0_2[NN], g_w1_2[NN], g_z0_2[NN], g_z1_2[NN];
__device__ int   g_si2[NN];
__device__ int   g_k2[NN];
__device__ float2 g_a2[NN];
__device__ float g_I0_2[NN*CD], g_S1_2[NN*CD];
__device__ float g_O0_2[NCH*CD], g_O1_2[NCH*CD];

__device__ ull   g_sc[HH1*NN];

__device__ float g_part[32*CD];

// ---------------- helpers ----------------
__device__ __forceinline__ ull fma2(ull a, ull b, ull c) {
    ull d;
    asm("fma.rn.f32x2 %0, %1, %2, %3;" : "=l"(d) : "l"(a), "l"(b), "l"(c));
    return d;
}
__device__ __forceinline__ ull pack2(float x, float y) {
    ull d;
    unsigned xi = __float_as_uint(x), yi = __float_as_uint(y);
    asm("mov.b64 %0, {%1, %2};" : "=l"(d) : "r"(xi), "r"(yi));
    return d;
}
__device__ __forceinline__ void unpack2(ull d, float& x, float& y) {
    unsigned lo, hi;
    asm("mov.b64 {%0, %1}, %2;" : "=r"(lo), "=r"(hi) : "l"(d));
    x = __uint_as_float(lo); y = __uint_as_float(hi);
}
__device__ __forceinline__ float elu1(float x) { return x > 0.f ? x : expm1f(x); }

// mma.sync bf16 (sm_80+ ISA; works on compute_103 base target)
__device__ __forceinline__ void mma_bf16(float* c, const uint32_t* a, const uint32_t* b) {
    asm volatile(
        "mma.sync.aligned.m16n8k16.row.col.f32.bf16.bf16.f32 "
        "{%0,%1,%2,%3}, {%4,%5,%6,%7}, {%8,%9}, {%0,%1,%2,%3};"
        : "+f"(c[0]), "+f"(c[1]), "+f"(c[2]), "+f"(c[3])
        : "r"(a[0]), "r"(a[1]), "r"(a[2]), "r"(a[3]), "r"(b[0]), "r"(b[1]));
}

// ============================================================================
// convA: split X fp32 -> bf16 hi/lo (coalesced)
// ============================================================================
__global__ void __launch_bounds__(256) convA_kernel(const float* __restrict__ X) {
    int i = blockIdx.x * 256 + threadIdx.x;             // float4 index
    float4 v = reinterpret_cast<const float4*>(X)[i];
    __nv_bfloat16 h[4], l[4];
    float f[4] = {v.x, v.y, v.z, v.w};
#pragma unroll
    for (int j = 0; j < 4; j++) {
        h[j] = __float2bfloat16(f[j]);
        l[j] = __float2bfloat16(f[j] - __bfloat162float(h[j]));
    }
    *reinterpret_cast<__nv_bfloat162*>(&g_XH[4 * i])     = __nv_bfloat162(h[0], h[1]);
    *reinterpret_cast<__nv_bfloat162*>(&g_XH[4 * i + 2]) = __nv_bfloat162(h[2], h[3]);
    *reinterpret_cast<__nv_bfloat162*>(&g_XL[4 * i])     = __nv_bfloat162(l[0], l[1]);
    *reinterpret_cast<__nv_bfloat162*>(&g_XL[4 * i + 2]) = __nv_bfloat162(l[2], l[3]);
}

// ============================================================================
// convB: W1 [768][512] -> Bt hi/lo [512][768] (smem tile transpose + split)
// ============================================================================
__global__ void __launch_bounds__(256) convB_kernel(const float* __restrict__ W1) {
    __shared__ float t[32][33];
    int tx = threadIdx.x & 31, ty = threadIdx.x >> 5;   // 32x8
    int k0 = blockIdx.x * 32, n0 = blockIdx.y * 32;
#pragma unroll
    for (int j = 0; j < 4; j++)
        t[ty + j * 8][tx] = W1[(k0 + ty + j * 8) * F1 + n0 + tx];
    __syncthreads();
#pragma unroll
    for (int j = 0; j < 4; j++) {
        float v = t[tx][ty + j * 8];
        __nv_bfloat16 h = __float2bfloat16(v);
        __nv_bfloat16 l = __float2bfloat16(v - __bfloat162float(h));
        g_BtH[(n0 + ty + j * 8) * DIN + k0 + tx] = h;
        g_BtL[(n0 + ty + j * 8) * DIN + k0 + tx] = l;
    }
}

// ============================================================================
// GEMM1 via mma.sync split-bf16 + fused s/t epilogue.
// grid (32, 4): bm = bx*128, head = by (BN=128==CD). 256 threads, 8 warps.
// Warp grid 2(m) x 4(n); warp tile 64x32; mma m16n8k16; 3 products per tile.
// smem: [2 stages][4 tiles: AH, AL, BH, BL][128 rows x 40 bf16 (80B stride)].
// ============================================================================
__global__ void __launch_bounds__(256)
gemm1_mma_kernel(const float* __restrict__ asrc, const float* __restrict__ adst) {
    extern __shared__ __align__(16) char sm[];
    const int tid = threadIdx.x;
    const int wid = tid >> 5, lane = tid & 31;
    const int gid = lane >> 2, tg = lane & 3;
    const int bm = blockIdx.x * 128, head = blockIdx.y, bn = head * 128;
    const int mw = wid & 1, nw = wid >> 1;
    const int mwb = mw * 64, nwb = nw * 32;

    float acc[4][4][4];
#pragma unroll
    for (int mi = 0; mi < 4; mi++)
#pragma unroll
        for (int ni = 0; ni < 4; ni++)
#pragma unroll
            for (int q = 0; q < 4; q++) acc[mi][ni][q] = 0.f;

    const __nv_bfloat16* srcs[4] = {g_XH, g_XL, g_BtH, g_BtL};
    const int rb[4] = {bm, bm, bn, bn};

    float4 pre[8];
    // prefetch chunk 0
#pragma unroll
    for (int t8 = 0; t8 < 8; t8++) {
        int tI = t8 >> 1;
        int i = (t8 & 1) * 256 + tid;
        int row = i >> 2, f4 = i & 3;
        pre[t8] = *reinterpret_cast<const float4*>(
            &srcs[tI][(size_t)(rb[tI] + row) * DIN + f4 * 8]);
    }
    // store chunk 0 into stage 0
#pragma unroll
    for (int t8 = 0; t8 < 8; t8++) {
        int tI = t8 >> 1;
        int i = (t8 & 1) * 256 + tid;
        int row = i >> 2, f4 = i & 3;
        *reinterpret_cast<float4*>(sm + (size_t)tI * TILEB + row * 80 + f4 * 16) = pre[t8];
    }
    __syncthreads();

    for (int ch = 0; ch < NCH1; ch++) {
        const int cur = ch & 1;
        char* tAH = sm + (size_t)(cur * 4 + 0) * TILEB;
        char* tAL = sm + (size_t)(cur * 4 + 1) * TILEB;
        char* tBH = sm + (size_t)(cur * 4 + 2) * TILEB;
        char* tBL = sm + (size_t)(cur * 4 + 3) * TILEB;

        if (ch + 1 < NCH1) {
            const int k0 = (ch + 1) * BK1;
#pragma unroll
            for (int t8 = 0; t8 < 8; t8++) {
                int tI = t8 >> 1;
                int i = (t8 & 1) * 256 + tid;
                int row = i >> 2, f4 = i & 3;
                pre[t8] = *reinterpret_cast<const float4*>(
                    &srcs[tI][(size_t)(rb[tI] + row) * DIN + k0 + f4 * 8]);
            }
        }

#pragma unroll
        for (int ks = 0; ks < 2; ks++) {
            const int kk = ks * 16;
            uint32_t aH[4][4], aL[4][4];
#pragma unroll
            for (int mi = 0; mi < 4; mi++) {
                int r0 = mwb + mi * 16 + gid;
                int co = (kk + tg * 2) * 2;
                aH[mi][0] = *reinterpret_cast<const uint32_t*>(tAH + r0 * 80 + co);
                aH[mi][1] = *reinterpret_cast<const uint32_t*>(tAH + (r0 + 8) * 80 + co);
                aH[mi][2] = *reinterpret_cast<const uint32_t*>(tAH + r0 * 80 + co + 16);
                aH[mi][3] = *reinterpret_cast<const uint32_t*>(tAH + (r0 + 8) * 80 + co + 16);
                aL[mi][0] = *reinterpret_cast<const uint32_t*>(tAL + r0 * 80 + co);
                aL[mi][1] = *reinterpret_cast<const uint32_t*>(tAL + (r0 + 8) * 80 + co);
                aL[mi][2] = *reinterpret_cast<const uint32_t*>(tAL + r0 * 80 + co + 16);
                aL[mi][3] = *reinterpret_cast<const uint32_t*>(tAL + (r0 + 8) * 80 + co + 16);
            }
            uint32_t bH[4][2], bL[4][2];
#pragma unroll
            for (int ni = 0; ni < 4; ni++) {
                int c0 = nwb + ni * 8 + gid;
                int co = (kk + tg * 2) * 2;
                bH[ni][0] = *reinterpret_cast<const uint32_t*>(tBH + c0 * 80 + co);
                bH[ni][1] = *reinterpret_cast<const uint32_t*>(tBH + c0 * 80 + co + 16);
                bL[ni][0] = *reinterpret_cast<const uint32_t*>(tBL + c0 * 80 + co);
                bL[ni][1] = *reinterpret_cast<const uint32_t*>(tBL + c0 * 80 + co + 16);
            }
#pragma unroll
            for (int mi = 0; mi < 4; mi++)
#pragma unroll
                for (int ni = 0; ni < 4; ni++) {
                    mma_bf16(acc[mi][ni], aH[mi], bH[ni]);
                    mma_bf16(acc[mi][ni], aH[mi], bL[ni]);
                    mma_bf16(acc[mi][ni], aL[mi], bH[ni]);
                }
        }

        if (ch + 1 < NCH1) {
            const int nxt = cur ^ 1;
#pragma unroll
            for (int t8 = 0; t8 < 8; t8++) {
                int tI = t8 >> 1;
                int i = (t8 & 1) * 256 + tid;
                int row = i >> 2, f4 = i & 3;
                *reinterpret_cast<float4*>(sm + (size_t)(nxt * 4 + tI) * TILEB +
                                           row * 80 + f4 * 16) = pre[t8];
            }
        }
        __syncthreads();
    }

    // epilogue: store h1, per-row s/t partials, cross-warp reduce via smem
    float* sredS = reinterpret_cast<float*>(sm);            // [128][4]
    float* sredT = reinterpret_cast<float*>(sm) + 512;      // [128][4]

#pragma unroll
    for (int mi = 0; mi < 4; mi++) {
        int r0 = mwb + mi * 16 + gid;
        float sp0 = 0.f, sp1 = 0.f, tp0 = 0.f, tp1 = 0.f;
#pragma unroll
        for (int ni = 0; ni < 4; ni++) {
            int col = nwb + ni * 8 + tg * 2;
            float2 av = *reinterpret_cast<const float2*>(&asrc[head * CD + col]);
            float2 dv = *reinterpret_cast<const float2*>(&adst[head * CD + col]);
            *reinterpret_cast<float2*>(&g_h1[(size_t)(bm + r0) * F1 + bn + col]) =
                make_float2(acc[mi][ni][0], acc[mi][ni][1]);
            *reinterpret_cast<float2*>(&g_h1[(size_t)(bm + r0 + 8) * F1 + bn + col]) =
                make_float2(acc[mi][ni][2], acc[mi][ni][3]);
            sp0 += acc[mi][ni][0] * av.x + acc[mi][ni][1] * av.y;
            tp0 += acc[mi][ni][0] * dv.x + acc[mi][ni][1] * dv.y;
            sp1 += acc[mi][ni][2] * av.x + acc[mi][ni][3] * av.y;
            tp1 += acc[mi][ni][2] * dv.x + acc[mi][ni][3] * dv.y;
        }
        // reduce over the 4 quad lanes (tg)
#pragma unroll
        for (int o = 1; o < 4; o <<= 1) {
            sp0 += __shfl_xor_sync(0xffffffffu, sp0, o);
            tp0 += __shfl_xor_sync(0xffffffffu, tp0, o);
            sp1 += __shfl_xor_sync(0xffffffffu, sp1, o);
            tp1 += __shfl_xor_sync(0xffffffffu, tp1, o);
        }
        if (mi == 0 && tg == 0) {} // no-op placeholder for scheduling
        if (tg == 0) {
            if (mi == 0) { /* first use of sred must be after syncthreads below */ }
        }
        // defer smem writes until after barrier (store into registers array)
        acc[mi][0][0] = sp0; acc[mi][0][1] = tp0;   // reuse acc storage
        acc[mi][0][2] = sp1; acc[mi][0][3] = tp1;
    }
    __syncthreads();   // all tile reads done; safe to reuse smem
#pragma unroll
    for (int mi = 0; mi < 4; mi++) {
        int r0 = mwb + mi * 16 + gid;
        if (tg == 0) {
            sredS[r0 * 4 + nw] = acc[mi][0][0];
            sredT[r0 * 4 + nw] = acc[mi][0][1];
            sredS[(r0 + 8) * 4 + nw] = acc[mi][0][2];
            sredT[(r0 + 8) * 4 + nw] = acc[mi][0][3];
        }
    }
    __syncthreads();
    if (tid < 128) {
        float s = sredS[tid * 4] + sredS[tid * 4 + 1] + sredS[tid * 4 + 2] + sredS[tid * 4 + 3];
        float t = sredT[tid * 4] + sredT[tid * 4 + 1] + sredT[tid * 4 + 2] + sredT[tid * 4 + 3];
        g_s1[head * NN + bm + tid] = s;
        g_t1[head * NN + bm + tid] = t;
    }
}

// ============================================================================
// GEMM2 (fp32 FFMA2) + fused s/t epilogue. TM=2, BM=32.
// ============================================================================
template<int TM>
__global__ void __launch_bounds__(256)
gemm_st_kernel(const float* __restrict__ B,
               const float* __restrict__ asrc, const float* __restrict__ adst,
               int M, int N, int K) {
    constexpr int BN = 128, BK = 16;
    constexpr int BM = 16 * TM;
    constexpr int ASTRIDE = BM + 4;
    constexpr int NA = (BM * 4 + 255) / 256;
    const float* A = g_x1;
    float* C  = g_h2;
    float* gs = g_s2;
    float* gt = g_t2;

    __shared__ __align__(16) float As[2][BK][ASTRIDE];
    __shared__ __align__(16) float Bs[2][BK][BN];

    const int tid = threadIdx.x;
    const int bm = blockIdx.x * BM, bn = blockIdx.y * BN;
    const int head = blockIdx.y;
    const int nt = tid & 15, mt = tid >> 4;
    const int m0 = mt * TM;

    ull acc[TM][4];
#pragma unroll
    for (int i = 0; i < TM; i++)
#pragma unroll
        for (int u = 0; u < 4; u++) acc[i][u] = 0ull;

    float4 apre[NA], bpre[2];
#pragma unroll
    for (int j = 0; j < NA; j++) {
        int idx = tid + j * 256;
        if (idx < BM * 4) {
            int row = idx >> 2, c4 = idx & 3;
            apre[j] = *reinterpret_cast<const float4*>(&A[(bm + row) * K + c4 * 4]);
        }
    }
#pragma unroll
    for (int j = 0; j < 2; j++) {
        int idx = tid + j * 256;
        int row = idx >> 5, c4 = idx & 31;
        bpre[j] = *reinterpret_cast<const float4*>(&B[row * N + bn + c4 * 4]);
    }
#pragma unroll
    for (int j = 0; j < NA; j++) {
        int idx = tid + j * 256;
        if (idx < BM * 4) {
            int row = idx >> 2, c4 = idx & 3;
#pragma unroll
            for (int w = 0; w < 4; w++) As[0][c4 * 4 + w][row] = (&apre[j].x)[w];
        }
    }
#pragma unroll
    for (int j = 0; j < 2; j++) {
        int idx = tid + j * 256;
        int row = idx >> 5, c4 = idx & 31;
        *reinterpret_cast<float4*>(&Bs[0][row][c4 * 4]) = bpre[j];
    }
    __syncthreads();

    const int ktiles = K / BK;
    for (int t = 0; t < ktiles; t++) {
        const int cur = t & 1;
        if (t + 1 < ktiles) {
            const int k0 = (t + 1) * BK;
#pragma unroll
            for (int j = 0; j < NA; j++) {
                int idx = tid + j * 256;
                if (idx < BM * 4) {
                    int row = idx >> 2, c4 = idx & 3;
                    apre[j] = *reinterpret_cast<const float4*>(&A[(bm + row) * K + k0 + c4 * 4]);
                }
            }
#pragma unroll
            for (int j = 0; j < 2; j++) {
                int idx = tid + j * 256;
                int row = idx >> 5, c4 = idx & 31;
                bpre[j] = *reinterpret_cast<const float4*>(&B[(k0 + row) * N + bn + c4 * 4]);
            }
        }
#pragma unroll
        for (int kk = 0; kk < BK; kk++) {
            float a[TM];
            float2 t0 = *reinterpret_cast<const float2*>(&As[cur][kk][m0]);
            a[0] = t0.x; a[1] = t0.y;
            ulonglong2 bb0 = *reinterpret_cast<const ulonglong2*>(&Bs[cur][kk][nt * 8]);
            ulonglong2 bb1 = *reinterpret_cast<const ulonglong2*>(&Bs[cur][kk][nt * 8 + 4]);
#pragma unroll
            for (int i = 0; i < TM; i++) {
                ull a2 = pack2(a[i], a[i]);
                acc[i][0] = fma2(a2, bb0.x, acc[i][0]);
                acc[i][1] = fma2(a2, bb0.y, acc[i][1]);
                acc[i][2] = fma2(a2, bb1.x, acc[i][2]);
                acc[i][3] = fma2(a2, bb1.y, acc[i][3]);
            }
        }
        if (t + 1 < ktiles) {
            const int nxt = cur ^ 1;
#pragma unroll
            for (int j = 0; j < NA; j++) {
                int idx = tid + j * 256;
                if (idx < BM * 4) {
                    int row = idx >> 2, c4 = idx & 3;
#pragma unroll
                    for (int w = 0; w < 4; w++) As[nxt][c4 * 4 + w][row] = (&apre[j].x)[w];
                }
            }
#pragma unroll
            for (int j = 0; j < 2; j++) {
                int idx = tid + j * 256;
                int row = idx >> 5, c4 = idx & 31;
                *reinterpret_cast<float4*>(&Bs[nxt][row][c4 * 4]) = bpre[j];
            }
        }
        __syncthreads();
    }

    float4 asv0 = *reinterpret_cast<const float4*>(&asrc[head * CD + nt * 8]);
    float4 asv1 = *reinterpret_cast<const float4*>(&asrc[head * CD + nt * 8 + 4]);
    float4 adv0 = *reinterpret_cast<const float4*>(&adst[head * CD + nt * 8]);
    float4 adv1 = *reinterpret_cast<const float4*>(&adst[head * CD + nt * 8 + 4]);

#pragma unroll
    for (int i = 0; i < TM; i++) {
        float x0, x1, x2, x3, x4, x5, x6, x7;
        unpack2(acc[i][0], x0, x1);
        unpack2(acc[i][1], x2, x3);
        unpack2(acc[i][2], x4, x5);
        unpack2(acc[i][3], x6, x7);
        *reinterpret_cast<float4*>(&C[(bm + m0 + i) * N + bn + nt * 8]) =
            make_float4(x0, x1, x2, x3);
        *reinterpret_cast<float4*>(&C[(bm + m0 + i) * N + bn + nt * 8 + 4]) =
            make_float4(x4, x5, x6, x7);
        float sp = x0*asv0.x + x1*asv0.y + x2*asv0.z + x3*asv0.w
                 + x4*asv1.x + x5*asv1.y + x6*asv1.z + x7*asv1.w;
        float tp = x0*adv0.x + x1*adv0.y + x2*adv0.z + x3*adv0.w
                 + x4*adv1.x + x5*adv1.y + x6*adv1.z + x7*adv1.w;
#pragma unroll
        for (int o = 1; o < 16; o <<= 1) {
            sp += __shfl_xor_sync(0xffffffffu, sp, o);
            tp += __shfl_xor_sync(0xffffffffu, tp, o);
        }
        if (nt == 0) {
            gs[head * NN + bm + m0 + i] = sp;
            gt[head * NN + bm + m0 + i] = tp;
        }
    }
}

// ============================================================================
// Sort stage 1: bitonic sort of 1024-element chunks
// ============================================================================
__device__ __forceinline__ void cswap(ull& a, ull& b, bool asc) {
    if ((a > b) == asc) { ull t = a; a = b; b = t; }
}

__global__ void __launch_bounds__(256)
sortchunk_kernel(int layer) {
    const float* s = (layer == 0) ? g_s1 : g_s2;
    const int head = blockIdx.y, chunk = blockIdx.x;
    const int tid = threadIdx.x;
    __shared__ ull kv[SC];

    const int gbase = head * NN + chunk * SC;
#pragma unroll
    for (int e = 0; e < 4; e++) {
        int i = tid + e * 256;
        unsigned u = __float_as_uint(s[gbase + i]);
        u = (u & 0x80000000u) ? ~u : (u | 0x80000000u);
        kv[i] = ((ull)u << 32) | (unsigned)(chunk * SC + i);
    }
    __syncthreads();

    {
        int i0 = 4 * tid;
        ull v0 = kv[i0], v1 = kv[i0 + 1], v2 = kv[i0 + 2], v3 = kv[i0 + 3];
        cswap(v0, v1, true); cswap(v2, v3, false);
        bool asc = ((i0 & 4) == 0);
        cswap(v0, v2, asc); cswap(v1, v3, asc);
        cswap(v0, v1, asc); cswap(v2, v3, asc);
        kv[i0] = v0; kv[i0 + 1] = v1; kv[i0 + 2] = v2; kv[i0 + 3] = v3;
    }
    __syncthreads();

    for (int k = 8; k <= SC; k <<= 1) {
        for (int j = k >> 1; j >= 4; j >>= 1) {
#pragma unroll
            for (int e = 0; e < 4; e++) {
                int i = tid + e * 256;
                if ((i & j) == 0) {
                    int p = i | j;
                    ull a = kv[i], b = kv[p];
                    bool asc = ((i & k) == 0);
                    if ((a > b) == asc) { kv[i] = b; kv[p] = a; }
                }
            }
            __syncthreads();
        }
        {
            int i0 = 4 * tid;
            ull v0 = kv[i0], v1 = kv[i0 + 1], v2 = kv[i0 + 2], v3 = kv[i0 + 3];
            bool asc = ((i0 & k) == 0);
            cswap(v0, v2, asc); cswap(v1, v3, asc);
            cswap(v0, v1, asc); cswap(v2, v3, asc);
            kv[i0] = v0; kv[i0 + 1] = v1; kv[i0 + 2] = v2; kv[i0 + 3] = v3;
        }
        __syncthreads();
    }

#pragma unroll
    for (int e = 0; e < 4; e++) {
        int i = tid + e * 256;
        g_sc[(head * NSC + chunk) * SC + i] = kv[i];
    }
}

// ============================================================================
// Sort stage 2: rank-merge (galloping, exact) + fused weights
// ============================================================================
__global__ void __launch_bounds__(256)
merge_kernel(int layer, int H) {
    float* ss = (layer == 0) ? g_ss1 : g_ss2;
    int*   si = (layer == 0) ? g_si1 : g_si2;
    float* w0 = (layer == 0) ? g_w0_1 : g_w0_2;
    float* w1 = (layer == 0) ? g_w1_1 : g_w1_2;

    int gid = blockIdx.x * 256 + threadIdx.x;
    if (gid >= H * NN) return;
    int head = gid >> 12;
    int i = gid & (NN - 1);
    int c = i >> 10, p = i & (SC - 1);

    const ull* base = g_sc + (size_t)head * NN;
    ull v = base[c * SC + p];

    const ull* oth[3];
    int cc = 0;
#pragma unroll
    for (int q = 0; q < 4; q++) if (q != c) oth[cc++] = base + q * SC;

    int p0 = 0, p1 = 0, p2 = 0;
#pragma unroll
    for (int step = SC; step >= 1; step >>= 1) {
        bool g0 = (p0 + step <= SC) && (__ldg(&oth[0][p0 + step - 1]) < v);
        bool g1 = (p1 + step <= SC) && (__ldg(&oth[1][p1 + step - 1]) < v);
        bool g2 = (p2 + step <= SC) && (__ldg(&oth[2][p2 + step - 1]) < v);
        if (g0) p0 += step;
        if (g1) p1 += step;
        if (g2) p2 += step;
    }
    int rank = p + p0 + p1 + p2;

    unsigned ku = (unsigned)(v >> 32);
    float f = (ku & 0x80000000u) ? __uint_as_float(ku ^ 0x80000000u)
                                 : __uint_as_float(~ku);
    ss[head * NN + rank] = f;
    si[head * NN + rank] = (int)(v & 0xffffffffu);
    w0[head * NN + rank] = expf(0.2f * f);
    w1[head * NN + rank] = expf(f);
}

// ============================================================================
// zscan: inclusive prefix (w0) / suffix (w1) scans, shfl-based
// ============================================================================
__global__ void __launch_bounds__(1024)
zscan_kernel(int layer) {
    const int dir = blockIdx.x, head = blockIdx.y;
    const float* w = (layer == 0) ? (dir == 0 ? g_w0_1 : g_w1_1)
                                  : (dir == 0 ? g_w0_2 : g_w1_2);
    float* z = (layer == 0) ? (dir == 0 ? g_z0_1 : g_z1_1)
                            : (dir == 0 ? g_z0_2 : g_z1_2);

    const int tid = threadIdx.x;
    const int lane = tid & 31, warp = tid >> 5;
    __shared__ float wsum[32], woff[32];

    const int i0 = 4 * tid;
    float4 v = *reinterpret_cast<const float4*>(&w[head * NN + i0]);

    if (dir == 0) {
        float p0 = v.x, p1 = p0 + v.y, p2 = p1 + v.z, p3 = p2 + v.w;
        float x = p3;
#pragma unroll
        for (int o = 1; o < 32; o <<= 1) {
            float y = __shfl_up_sync(0xffffffffu, x, o);
            if (lane >= o) x += y;
        }
        float wexcl = x - p3;
        if (lane == 31) wsum[warp] = x;
        __syncthreads();
        if (warp == 0) {
            float t = wsum[lane];
#pragma unroll
            for (int o = 1; o < 32; o <<= 1) {
                float y = __shfl_up_sync(0xffffffffu, t, o);
                if (lane >= o) t += y;
            }
            woff[lane] = t - wsum[lane];
        }
        __syncthreads();
        float off = woff[warp] + wexcl;
        *reinterpret_cast<float4*>(&z[head * NN + i0]) =
            make_float4(p0 + off, p1 + off, p2 + off, p3 + off);
    } else {
        float q3 = v.w, q2 = q3 + v.z, q1 = q2 + v.y, q0 = q1 + v.x;
        float x = q0;
#pragma unroll
        for (int o = 1; o < 32; o <<= 1) {
            float y = __shfl_down_sync(0xffffffffu, x, o);
            if (lane + o < 32) x += y;
        }
        float wexcl = x - q0;
        if (lane == 0) wsum[warp] = x;
        __syncthreads();
        if (warp == 0) {
            float t = wsum[lane];
#pragma unroll
            for (int o = 1; o < 32; o <<= 1) {
                float y = __shfl_down_sync(0xffffffffu, t, o);
                if (lane + o < 32) t += y;
            }
            woff[lane] = t - wsum[lane];
        }
        __syncthreads();
        float off = woff[warp] + wexcl;
        *reinterpret_cast<float4*>(&z[head * NN + i0]) =
            make_float4(q0 + off, q1 + off, q2 + off, q3 + off);
    }
}

// ============================================================================
// ksearch: split points + per-(head,node) scalar coefficients
// ============================================================================
__global__ void __launch_bounds__(256)
ksearch_kernel(int layer, int H) {
    const float* t  = (layer == 0) ? g_t1 : g_t2;
    const float* ss = (layer == 0) ? g_ss1 : g_ss2;
    const float* z0 = (layer == 0) ? g_z0_1 : g_z0_2;
    const float* z1 = (layer == 0) ? g_z1_1 : g_z1_2;
    int*    kk = (layer == 0) ? g_k1 : g_k2;
    float2* aa = (layer == 0) ? g_a1 : g_a2;

    int gid = blockIdx.x * 256 + threadIdx.x;
    if (gid >= H * NN) return;
    int head = gid >> 12;
    const float* ssh = ss + head * NN;
    float tv = t[gid];
    float tau = -tv;
    int pos = 0;
#pragma unroll
    for (int step = NN; step >= 1; step >>= 1) {
        if (pos + step <= NN && __ldg(&ssh[pos + step - 1]) <= tau) pos += step;
    }
    kk[gid] = pos;

    float z0v = (pos > 0)  ? z0[head * NN + pos - 1] : 0.f;
    float z1v = (pos < NN) ? z1[head * NN + pos]     : 0.f;
    float et  = expf(tv);
    float et2 = expf(0.2f * tv);
    float inv = 1.f / (et * z1v + et2 * z0v);
    float a0 = (pos > 0)  ? et2 * inv : 0.f;
    float a1 = (pos < NN) ? et  * inv : 0.f;
    aa[gid] = make_float2(a0, a1);
}

// ============================================================================
// passA: chunked vector scans (MLP=16 gathers)
// ============================================================================
__global__ void __launch_bounds__(CD)
passA_kernel(int layer, int F) {
    const float* h  = (layer == 0) ? g_h1 : g_h2;
    const int*   si = (layer == 0) ? g_si1 : g_si2;
    const float* w0 = (layer == 0) ? g_w0_1 : g_w0_2;
    const float* w1 = (layer == 0) ? g_w1_1 : g_w1_2;
    float* I0 = (layer == 0) ? g_I0_1 : g_I0_2;
    float* S1 = (layer == 0) ? g_S1_1 : g_S1_2;

    const int chunk = blockIdx.x, head = blockIdx.y, dir = blockIdx.z;
    const int c = threadIdx.x;
    const int base = head * NN + chunk * CHUNK;

    __shared__ int   sj[CHUNK];
    __shared__ float sw[CHUNK];
    const float* wsel = (dir == 0) ? w0 : w1;
    for (int r = threadIdx.x; r < CHUNK; r += blockDim.x) {
        sj[r] = si[base + r] * F + head * CD;
        sw[r] = wsel[base + r];
    }
    __syncthreads();

    float acc = 0.f;
    if (dir == 0) {
        float* dst = I0 + (size_t)base * CD + c;
        for (int rr = 0; rr < CHUNK; rr += 16) {
            float v[16];
#pragma unroll
            for (int u = 0; u < 16; u++) v[u] = __ldg(&h[sj[rr + u] + c]);
#pragma unroll
            for (int u = 0; u < 16; u++) {
                acc = fmaf(sw[rr + u], v[u], acc);
                dst[(size_t)(rr + u) * CD] = acc;
            }
        }
    } else {
        float* dst = S1 + (size_t)base * CD + c;
        for (int rr = CHUNK - 16; rr >= 0; rr -= 16) {
            float v[16];
#pragma unroll
            for (int u = 15; u >= 0; u--) v[u] = __ldg(&h[sj[rr + u] + c]);
#pragma unroll
            for (int u = 15; u >= 0; u--) {
                acc = fmaf(sw[rr + u], v[u], acc);
                dst[(size_t)(rr + u) * CD] = acc;
            }
        }
    }
}

// ---------------- cross-chunk offsets ----------------
__global__ void passB_kernel(int layer) {
    const float* I0 = (layer == 0) ? g_I0_1 : g_I0_2;
    const float* S1 = (layer == 0) ? g_S1_1 : g_S1_2;
    float* O0 = (layer == 0) ? g_O0_1 : g_O0_2;
    float* O1 = (layer == 0) ? g_O1_1 : g_O1_2;

    int head = blockIdx.x, c = threadIdx.x;
    float acc = 0.f;
    for (int ch = 0; ch < NCH; ch++) {
        O0[(head * NCH + ch) * CD + c] = acc;
        acc += I0[(head * NN + ch * CHUNK + CHUNK - 1) * CD + c];
    }
    acc = 0.f;
    for (int ch = NCH - 1; ch >= 0; ch--) {
        O1[(head * NCH + ch) * CD + c] = acc;
        acc += S1[(head * NN + ch * CHUNK) * CD + c];
    }
}

// ---------------- lookup: 2 clamped table reads + 2 FMA + elu ----------------
__global__ void __launch_bounds__(CD)
lookup_kernel(int layer, const float* __restrict__ bias, int F) {
    const int*    kk = (layer == 0) ? g_k1 : g_k2;
    const float2* aa = (layer == 0) ? g_a1 : g_a2;
    const float* I0 = (layer == 0) ? g_I0_1 : g_I0_2;
    const float* S1 = (layer == 0) ? g_S1_1 : g_S1_2;
    const float* O0 = (layer == 0) ? g_O0_1 : g_O0_2;
    const float* O1 = (layer == 0) ? g_O1_1 : g_O1_2;
    float* xout = (layer == 0) ? g_x1 : g_x2;

    int head = blockIdx.y, c = threadIdx.x;
    float bv = bias[head * CD + c];

#pragma unroll 2
    for (int u = 0; u < 8; u++) {
        int i = blockIdx.x * 8 + u;
        int k = kk[head * NN + i];
        float2 a = aa[head * NN + i];

        int k0i = (k > 0) ? (k - 1) : 0;
        int k1i = (k < NN) ? k : (NN - 1);
        float A0 = I0[(size_t)(head * NN + k0i) * CD + c] +
                   O0[(head * NCH + k0i / CHUNK) * CD + c];
        float A1 = S1[(size_t)(head * NN + k1i) * CD + c] +
                   O1[(head * NCH + k1i / CHUNK) * CD + c];
        float o = fmaf(a.y, A1, fmaf(a.x, A0, bv));
        xout[i * F + head * CD + c] = elu1(o);
    }
}

// ---------------- column mean + FC ----------------
__global__ void colpart_kernel() {
    int b = blockIdx.x, c = threadIdx.x;
    float acc = 0.f;
    for (int r = 0; r < NN / 32; r++) acc += g_x2[(b * (NN / 32) + r) * CD + c];
    g_part[b * CD + c] = acc;
}
__global__ void __launch_bounds__(DIN)
colfinal_fc_kernel(const float* __restrict__ fcW, const float* __restrict__ fcb,
                   float* __restrict__ out) {
    __shared__ float m[CD];
    int tid = threadIdx.x;
    if (tid < CD) {
        float a = 0.f;
        for (int b = 0; b < 32; b++) a += g_part[b * CD + tid];
        m[tid] = a * (1.f / (float)NN);
    }
    __syncthreads();
    if (tid < DIN) {
        float acc = fcb[tid];
#pragma unroll 8
        for (int c = 0; c < CD; c++) acc = fmaf(m[c], fcW[c * DIN + tid], acc);
        out[tid] = acc;
    }
}

// ---------------- launch ----------------
extern "C" void kernel_launch(void* const* d_in, const int* in_sizes, int n_in,
                              void* d_out, int out_size) {
    const float* X   = (const float*)d_in[0];
    const float* W1  = (const float*)d_in[1];
    const float* as1 = (const float*)d_in[2];
    const float* ad1 = (const float*)d_in[3];
    const float* b1  = (const float*)d_in[4];
    const float* W2  = (const float*)d_in[5];
    const float* as2 = (const float*)d_in[6];
    const float* ad2 = (const float*)d_in[7];
    const float* b2  = (const float*)d_in[8];
    const float* fcW = (const float*)d_in[9];
    const float* fcb = (const float*)d_in[10];
    float* out = (float*)d_out;

    const int MMA_SMEM = 2 * 4 * TILEB;   // 81920 bytes
    cudaFuncSetAttribute(gemm1_mma_kernel,
                         cudaFuncAttributeMaxDynamicSharedMemorySize, MMA_SMEM);

    // Layer 1: split-bf16 mma.sync GEMM (M=4096, K=768, N=512)
    convA_kernel<<<(NN * DIN / 4) / 256, 256>>>(X);
    convB_kernel<<<dim3(DIN / 32, F1 / 32), 256>>>(W1);
    gemm1_mma_kernel<<<dim3(NN / 128, HH1), 256, MMA_SMEM>>>(as1, ad1);
    sortchunk_kernel<<<dim3(NSC, HH1), 256>>>(0);
    merge_kernel<<<(HH1 * NN) / 256, 256>>>(0, HH1);
    zscan_kernel<<<dim3(2, HH1), 1024>>>(0);
    ksearch_kernel<<<(HH1 * NN) / 256, 256>>>(0, HH1);
    passA_kernel<<<dim3(NCH, HH1, 2), CD>>>(0, F1);
    passB_kernel<<<HH1, CD>>>(0);
    lookup_kernel<<<dim3(NN / 8, HH1), CD>>>(0, b1, F1);

    // Layer 2: fp32 FFMA2 (M=4096, K=512, N=128)
    gemm_st_kernel<2><<<dim3(NN / 32, 1), 256>>>(W2, as2, ad2, NN, CD, F1);
    sortchunk_kernel<<<dim3(NSC, 1), 256>>>(1);
    merge_kernel<<<NN / 256, 256>>>(1, 1);
    zscan_kernel<<<dim3(2, 1), 1024>>>(1);
    ksearch_kernel<<<NN / 256, 256>>>(1, 1);
    passA_kernel<<<dim3(NCH, 1, 2), CD>>>(1, CD);
    passB_kernel<<<1, CD>>>(1);
    lookup_kernel<<<dim3(NN / 8, 1), CD>>>(1, b2, CD);

    // Mean + FC
    colpart_kernel<<<32, CD>>>();
    colfinal_fc_kernel<<<1, DIN>>>(fcW, fcb, out);
}

// round 13
// speedup vs baseline: 2.6945x; 1.1778x over previous
#include <cuda_runtime.h>
#include <cuda_bf16.h>
#include <stdint.h>
#include <math.h>

#define NN    4096
#define DIN   768
#define CD    128
#define HH1   4
#define F1    512
#define CHUNK 256
#define NCH   (NN/CHUNK)   // 16 (passA chunks)
#define SC    1024         // sort chunk size
#define NSC   4            // sort chunks
#define BK1   32           // mma gemm K-chunk
#define NCH1  (DIN/BK1)    // 24 (layer1); layer2 uses F1/BK1 = 16
#define TSTR  40           // smem row stride in bf16 elems (80B) -> conflict-free frags
#define TILEB (128*TSTR*2) // 10240 B per tile

typedef unsigned long long ull;

// ---------------- device scratch (no allocs allowed) ----------------
__device__ float g_h1[NN*F1];
__device__ float g_h2[NN*CD];
__device__ float g_x2[NN*CD];

__device__ __nv_bfloat16 g_XH[NN*DIN],  g_XL[NN*DIN];     // split X
__device__ __nv_bfloat16 g_BtH[F1*DIN], g_BtL[F1*DIN];    // split W1^T [512][768]
__device__ __nv_bfloat16 g_x1H[NN*F1],  g_x1L[NN*F1];     // split x1 (layer2 A)
__device__ __nv_bfloat16 g_Bt2H[CD*F1], g_Bt2L[CD*F1];    // split W2^T [128][512]

__device__ float g_s1[HH1*NN], g_t1[HH1*NN], g_ss1[HH1*NN];
__device__ float g_w0_1[HH1*NN], g_w1_1[HH1*NN], g_z0_1[HH1*NN], g_z1_1[HH1*NN];
__device__ int   g_si1[HH1*NN];
__device__ int   g_k1[HH1*NN];
__device__ float2 g_a1[HH1*NN];
__device__ float g_I0_1[HH1*NN*CD], g_S1_1[HH1*NN*CD];
__device__ float g_O0_1[HH1*NCH*CD], g_O1_1[HH1*NCH*CD];

__device__ float g_s2[NN], g_t2[NN], g_ss2[NN];
__device__ float g_w0_2[NN], g_w1_2[NN], g_z0_2[NN], g_z1_2[NN];
__device__ int   g_si2[NN];
__device__ int   g_k2[NN];
__device__ float2 g_a2[NN];
__device__ float g_I0_2[NN*CD], g_S1_2[NN*CD];
__device__ float g_O0_2[NCH*CD], g_O1_2[NCH*CD];

__device__ ull   g_sc[HH1*NN];

__device__ float g_part[32*CD];

// ---------------- helpers ----------------
__device__ __forceinline__ float elu1(float x) { return x > 0.f ? x : expm1f(x); }

// mma.sync bf16 (sm_80+ ISA; compiles on compute_103 base target)
__device__ __forceinline__ void mma_bf16(float* c, const uint32_t* a, const uint32_t* b) {
    asm volatile(
        "mma.sync.aligned.m16n8k16.row.col.f32.bf16.bf16.f32 "
        "{%0,%1,%2,%3}, {%4,%5,%6,%7}, {%8,%9}, {%0,%1,%2,%3};"
        : "+f"(c[0]), "+f"(c[1]), "+f"(c[2]), "+f"(c[3])
        : "r"(a[0]), "r"(a[1]), "r"(a[2]), "r"(a[3]), "r"(b[0]), "r"(b[1]));
}

// ============================================================================
// convA: split X fp32 -> bf16 hi/lo (coalesced)
// ============================================================================
__global__ void __launch_bounds__(256) convA_kernel(const float* __restrict__ X) {
    int i = blockIdx.x * 256 + threadIdx.x;             // float4 index
    float4 v = reinterpret_cast<const float4*>(X)[i];
    __nv_bfloat16 h[4], l[4];
    float f[4] = {v.x, v.y, v.z, v.w};
#pragma unroll
    for (int j = 0; j < 4; j++) {
        h[j] = __float2bfloat16(f[j]);
        l[j] = __float2bfloat16(f[j] - __bfloat162float(h[j]));
    }
    *reinterpret_cast<__nv_bfloat162*>(&g_XH[4 * i])     = __nv_bfloat162(h[0], h[1]);
    *reinterpret_cast<__nv_bfloat162*>(&g_XH[4 * i + 2]) = __nv_bfloat162(h[2], h[3]);
    *reinterpret_cast<__nv_bfloat162*>(&g_XL[4 * i])     = __nv_bfloat162(l[0], l[1]);
    *reinterpret_cast<__nv_bfloat162*>(&g_XL[4 * i + 2]) = __nv_bfloat162(l[2], l[3]);
}

// ============================================================================
// convB: W [R][C] -> Bt hi/lo [C][R] (smem tile transpose + split)
// layer 0: W1 [768][512] -> g_BtH/L ; layer 1: W2 [512][128] -> g_Bt2H/L
// ============================================================================
__global__ void __launch_bounds__(256) convB_kernel(const float* __restrict__ W, int layer) {
    const int R = (layer == 0) ? DIN : F1;
    const int C = (layer == 0) ? F1 : CD;
    __nv_bfloat16* dH = (layer == 0) ? g_BtH : g_Bt2H;
    __nv_bfloat16* dL = (layer == 0) ? g_BtL : g_Bt2L;
    __shared__ float t[32][33];
    int tx = threadIdx.x & 31, ty = threadIdx.x >> 5;   // 32x8
    int k0 = blockIdx.x * 32, n0 = blockIdx.y * 32;
#pragma unroll
    for (int j = 0; j < 4; j++)
        t[ty + j * 8][tx] = W[(k0 + ty + j * 8) * C + n0 + tx];
    __syncthreads();
#pragma unroll
    for (int j = 0; j < 4; j++) {
        float v = t[tx][ty + j * 8];
        __nv_bfloat16 h = __float2bfloat16(v);
        __nv_bfloat16 l = __float2bfloat16(v - __bfloat162float(h));
        dH[(size_t)(n0 + ty + j * 8) * R + k0 + tx] = h;
        dL[(size_t)(n0 + ty + j * 8) * R + k0 + tx] = l;
    }
}

// ============================================================================
// GEMM via mma.sync split-bf16 + fused s/t epilogue (both layers).
// grid (M/128, N/128): bm = bx*128, head = by. 256 threads, 8 warps.
// Warp grid 2(m) x 4(n); warp tile 64x32; mma m16n8k16; 3 products per tile.
// smem: [2 stages][4 tiles: AH, AL, BH, BL][128 rows x 40 bf16 (80B stride)].
// ============================================================================
__global__ void __launch_bounds__(256)
gemm_mma_kernel(int layer, const float* __restrict__ asrc, const float* __restrict__ adst) {
    extern __shared__ __align__(16) char sm[];
    const __nv_bfloat16* AH = (layer == 0) ? g_XH  : g_x1H;
    const __nv_bfloat16* AL = (layer == 0) ? g_XL  : g_x1L;
    const __nv_bfloat16* BH = (layer == 0) ? g_BtH : g_Bt2H;
    const __nv_bfloat16* BL = (layer == 0) ? g_BtL : g_Bt2L;
    float* Cout = (layer == 0) ? g_h1 : g_h2;
    float* gs   = (layer == 0) ? g_s1 : g_s2;
    float* gt   = (layer == 0) ? g_t1 : g_t2;
    const int ldk = (layer == 0) ? DIN : F1;
    const int ldc = (layer == 0) ? F1 : CD;
    const int nchunks = (layer == 0) ? NCH1 : (F1 / BK1);

    const int tid = threadIdx.x;
    const int wid = tid >> 5, lane = tid & 31;
    const int gid = lane >> 2, tg = lane & 3;
    const int bm = blockIdx.x * 128, head = blockIdx.y, bn = head * 128;
    const int mw = wid & 1, nw = wid >> 1;
    const int mwb = mw * 64, nwb = nw * 32;

    float acc[4][4][4];
#pragma unroll
    for (int mi = 0; mi < 4; mi++)
#pragma unroll
        for (int ni = 0; ni < 4; ni++)
#pragma unroll
            for (int q = 0; q < 4; q++) acc[mi][ni][q] = 0.f;

    const __nv_bfloat16* srcs[4] = {AH, AL, BH, BL};
    const int rb[4] = {bm, bm, bn, bn};

    float4 pre[8];
    // prefetch chunk 0
#pragma unroll
    for (int t8 = 0; t8 < 8; t8++) {
        int tI = t8 >> 1;
        int i = (t8 & 1) * 256 + tid;
        int row = i >> 2, f4 = i & 3;
        pre[t8] = *reinterpret_cast<const float4*>(
            &srcs[tI][(size_t)(rb[tI] + row) * ldk + f4 * 8]);
    }
    // store chunk 0 into stage 0
#pragma unroll
    for (int t8 = 0; t8 < 8; t8++) {
        int tI = t8 >> 1;
        int i = (t8 & 1) * 256 + tid;
        int row = i >> 2, f4 = i & 3;
        *reinterpret_cast<float4*>(sm + (size_t)tI * TILEB + row * 80 + f4 * 16) = pre[t8];
    }
    __syncthreads();

    for (int ch = 0; ch < nchunks; ch++) {
        const int cur = ch & 1;
        char* tAH = sm + (size_t)(cur * 4 + 0) * TILEB;
        char* tAL = sm + (size_t)(cur * 4 + 1) * TILEB;
        char* tBH = sm + (size_t)(cur * 4 + 2) * TILEB;
        char* tBL = sm + (size_t)(cur * 4 + 3) * TILEB;

        if (ch + 1 < nchunks) {
            const int k0 = (ch + 1) * BK1;
#pragma unroll
            for (int t8 = 0; t8 < 8; t8++) {
                int tI = t8 >> 1;
                int i = (t8 & 1) * 256 + tid;
                int row = i >> 2, f4 = i & 3;
                pre[t8] = *reinterpret_cast<const float4*>(
                    &srcs[tI][(size_t)(rb[tI] + row) * ldk + k0 + f4 * 8]);
            }
        }

#pragma unroll
        for (int ks = 0; ks < 2; ks++) {
            const int kk = ks * 16;
            uint32_t aH[4][4], aL[4][4];
#pragma unroll
            for (int mi = 0; mi < 4; mi++) {
                int r0 = mwb + mi * 16 + gid;
                int co = (kk + tg * 2) * 2;
                aH[mi][0] = *reinterpret_cast<const uint32_t*>(tAH + r0 * 80 + co);
                aH[mi][1] = *reinterpret_cast<const uint32_t*>(tAH + (r0 + 8) * 80 + co);
                aH[mi][2] = *reinterpret_cast<const uint32_t*>(tAH + r0 * 80 + co + 16);
                aH[mi][3] = *reinterpret_cast<const uint32_t*>(tAH + (r0 + 8) * 80 + co + 16);
                aL[mi][0] = *reinterpret_cast<const uint32_t*>(tAL + r0 * 80 + co);
                aL[mi][1] = *reinterpret_cast<const uint32_t*>(tAL + (r0 + 8) * 80 + co);
                aL[mi][2] = *reinterpret_cast<const uint32_t*>(tAL + r0 * 80 + co + 16);
                aL[mi][3] = *reinterpret_cast<const uint32_t*>(tAL + (r0 + 8) * 80 + co + 16);
            }
            uint32_t bH[4][2], bL[4][2];
#pragma unroll
            for (int ni = 0; ni < 4; ni++) {
                int c0 = nwb + ni * 8 + gid;
                int co = (kk + tg * 2) * 2;
                bH[ni][0] = *reinterpret_cast<const uint32_t*>(tBH + c0 * 80 + co);
                bH[ni][1] = *reinterpret_cast<const uint32_t*>(tBH + c0 * 80 + co + 16);
                bL[ni][0] = *reinterpret_cast<const uint32_t*>(tBL + c0 * 80 + co);
                bL[ni][1] = *reinterpret_cast<const uint32_t*>(tBL + c0 * 80 + co + 16);
            }
#pragma unroll
            for (int mi = 0; mi < 4; mi++)
#pragma unroll
                for (int ni = 0; ni < 4; ni++) {
                    mma_bf16(acc[mi][ni], aH[mi], bH[ni]);
                    mma_bf16(acc[mi][ni], aH[mi], bL[ni]);
                    mma_bf16(acc[mi][ni], aL[mi], bH[ni]);
                }
        }

        if (ch + 1 < nchunks) {
            const int nxt = cur ^ 1;
#pragma unroll
            for (int t8 = 0; t8 < 8; t8++) {
                int tI = t8 >> 1;
                int i = (t8 & 1) * 256 + tid;
                int row = i >> 2, f4 = i & 3;
                *reinterpret_cast<float4*>(sm + (size_t)(nxt * 4 + tI) * TILEB +
                                           row * 80 + f4 * 16) = pre[t8];
            }
        }
        __syncthreads();
    }

    // epilogue: store C, per-row s/t partials, cross-warp reduce via smem
    float* sredS = reinterpret_cast<float*>(sm);            // [128][4]
    float* sredT = reinterpret_cast<float*>(sm) + 512;      // [128][4]

#pragma unroll
    for (int mi = 0; mi < 4; mi++) {
        int r0 = mwb + mi * 16 + gid;
        float sp0 = 0.f, sp1 = 0.f, tp0 = 0.f, tp1 = 0.f;
#pragma unroll
        for (int ni = 0; ni < 4; ni++) {
            int col = nwb + ni * 8 + tg * 2;
            float2 av = *reinterpret_cast<const float2*>(&asrc[head * CD + col]);
            float2 dv = *reinterpret_cast<const float2*>(&adst[head * CD + col]);
            *reinterpret_cast<float2*>(&Cout[(size_t)(bm + r0) * ldc + bn + col]) =
                make_float2(acc[mi][ni][0], acc[mi][ni][1]);
            *reinterpret_cast<float2*>(&Cout[(size_t)(bm + r0 + 8) * ldc + bn + col]) =
                make_float2(acc[mi][ni][2], acc[mi][ni][3]);
            sp0 += acc[mi][ni][0] * av.x + acc[mi][ni][1] * av.y;
            tp0 += acc[mi][ni][0] * dv.x + acc[mi][ni][1] * dv.y;
            sp1 += acc[mi][ni][2] * av.x + acc[mi][ni][3] * av.y;
            tp1 += acc[mi][ni][2] * dv.x + acc[mi][ni][3] * dv.y;
        }
#pragma unroll
        for (int o = 1; o < 4; o <<= 1) {
            sp0 += __shfl_xor_sync(0xffffffffu, sp0, o);
            tp0 += __shfl_xor_sync(0xffffffffu, tp0, o);
            sp1 += __shfl_xor_sync(0xffffffffu, sp1, o);
            tp1 += __shfl_xor_sync(0xffffffffu, tp1, o);
        }
        acc[mi][0][0] = sp0; acc[mi][0][1] = tp0;   // stash in acc storage
        acc[mi][0][2] = sp1; acc[mi][0][3] = tp1;
    }
    __syncthreads();   // all tile reads done; safe to reuse smem
#pragma unroll
    for (int mi = 0; mi < 4; mi++) {
        int r0 = mwb + mi * 16 + gid;
        if (tg == 0) {
            sredS[r0 * 4 + nw] = acc[mi][0][0];
            sredT[r0 * 4 + nw] = acc[mi][0][1];
            sredS[(r0 + 8) * 4 + nw] = acc[mi][0][2];
            sredT[(r0 + 8) * 4 + nw] = acc[mi][0][3];
        }
    }
    __syncthreads();
    if (tid < 128) {
        float s = sredS[tid * 4] + sredS[tid * 4 + 1] + sredS[tid * 4 + 2] + sredS[tid * 4 + 3];
        float t = sredT[tid * 4] + sredT[tid * 4 + 1] + sredT[tid * 4 + 2] + sredT[tid * 4 + 3];
        gs[head * NN + bm + tid] = s;
        gt[head * NN + bm + tid] = t;
    }
}

// ============================================================================
// Sort stage 1: bitonic sort of 1024-element chunks.
// 4 elems/thread (contiguous). j<=2 in regs, 4<=j<=64 via shfl_xor,
// j>=128 via smem (only 6 stages total) — sync count ~10 vs 36.
// ============================================================================
__device__ __forceinline__ void cswap(ull& a, ull& b, bool asc) {
    if ((a > b) == asc) { ull t = a; a = b; b = t; }
}

__global__ void __launch_bounds__(256)
sortchunk_kernel(int layer) {
    const float* s = (layer == 0) ? g_s1 : g_s2;
    const int head = blockIdx.y, chunk = blockIdx.x;
    const int tid = threadIdx.x;
    const int i0 = 4 * tid;
    __shared__ ull kv[SC];

    ull v[4];
    const int gbase = head * NN + chunk * SC;
#pragma unroll
    for (int e = 0; e < 4; e++) {
        unsigned u = __float_as_uint(s[gbase + i0 + e]);
        u = (u & 0x80000000u) ? ~u : (u | 0x80000000u);
        v[e] = ((ull)u << 32) | (unsigned)(chunk * SC + i0 + e);
    }

    // k=2, k=4 in registers
    cswap(v[0], v[1], true); cswap(v[2], v[3], false);
    {
        bool asc = ((i0 & 4) == 0);
        cswap(v[0], v[2], asc); cswap(v[1], v[3], asc);
        cswap(v[0], v[1], asc); cswap(v[2], v[3], asc);
    }

    // k = 8..128: all stages via shfl + regs (no smem, no syncs)
#pragma unroll
    for (int k = 8; k <= 128; k <<= 1) {
        const bool asc = ((i0 & k) == 0);
#pragma unroll
        for (int j = k >> 1; j >= 4; j >>= 1) {
            const bool keepmin = (((i0 & j) == 0) == asc);
#pragma unroll
            for (int e = 0; e < 4; e++) {
                ull o = __shfl_xor_sync(0xffffffffu, v[e], j >> 2);
                ull mn = (v[e] < o) ? v[e] : o;
                ull mx = (v[e] < o) ? o : v[e];
                v[e] = keepmin ? mn : mx;
            }
        }
        cswap(v[0], v[2], asc); cswap(v[1], v[3], asc);
        cswap(v[0], v[1], asc); cswap(v[2], v[3], asc);
    }

    // k = 256, 512, 1024: j>=128 via smem, then shfl/regs
    for (int k = 256; k <= SC; k <<= 1) {
#pragma unroll
        for (int e = 0; e < 4; e++) kv[i0 + e] = v[e];
        __syncthreads();
        for (int j = k >> 1; j >= 128; j >>= 1) {
#pragma unroll
            for (int e = 0; e < 4; e++) {
                int i = tid + e * 256;
                if ((i & j) == 0) {
                    int p = i | j;
                    ull a = kv[i], b = kv[p];
                    bool asc2 = ((i & k) == 0);
                    if ((a > b) == asc2) { kv[i] = b; kv[p] = a; }
                }
            }
            __syncthreads();
        }
#pragma unroll
        for (int e = 0; e < 4; e++) v[e] = kv[i0 + e];
        const bool asc = ((i0 & k) == 0);
#pragma unroll
        for (int j = 64; j >= 4; j >>= 1) {
            const bool keepmin = (((i0 & j) == 0) == asc);
#pragma unroll
            for (int e = 0; e < 4; e++) {
                ull o = __shfl_xor_sync(0xffffffffu, v[e], j >> 2);
                ull mn = (v[e] < o) ? v[e] : o;
                ull mx = (v[e] < o) ? o : v[e];
                v[e] = keepmin ? mn : mx;
            }
        }
        cswap(v[0], v[2], asc); cswap(v[1], v[3], asc);
        cswap(v[0], v[1], asc); cswap(v[2], v[3], asc);
        __syncthreads();   // protect kv before next k's store
    }

#pragma unroll
    for (int e = 0; e < 4; e++)
        g_sc[(head * NSC + chunk) * SC + i0 + e] = v[e];
}

// ============================================================================
// Sort stage 2: rank-merge (galloping, exact) + fused weights
// ============================================================================
__global__ void __launch_bounds__(256)
merge_kernel(int layer, int H) {
    float* ss = (layer == 0) ? g_ss1 : g_ss2;
    int*   si = (layer == 0) ? g_si1 : g_si2;
    float* w0 = (layer == 0) ? g_w0_1 : g_w0_2;
    float* w1 = (layer == 0) ? g_w1_1 : g_w1_2;

    int gid = blockIdx.x * 256 + threadIdx.x;
    if (gid >= H * NN) return;
    int head = gid >> 12;
    int i = gid & (NN - 1);
    int c = i >> 10, p = i & (SC - 1);

    const ull* base = g_sc + (size_t)head * NN;
    ull v = base[c * SC + p];

    const ull* oth[3];
    int cc = 0;
#pragma unroll
    for (int q = 0; q < 4; q++) if (q != c) oth[cc++] = base + q * SC;

    int p0 = 0, p1 = 0, p2 = 0;
#pragma unroll
    for (int step = SC; step >= 1; step >>= 1) {
        bool g0 = (p0 + step <= SC) && (__ldg(&oth[0][p0 + step - 1]) < v);
        bool g1 = (p1 + step <= SC) && (__ldg(&oth[1][p1 + step - 1]) < v);
        bool g2 = (p2 + step <= SC) && (__ldg(&oth[2][p2 + step - 1]) < v);
        if (g0) p0 += step;
        if (g1) p1 += step;
        if (g2) p2 += step;
    }
    int rank = p + p0 + p1 + p2;

    unsigned ku = (unsigned)(v >> 32);
    float f = (ku & 0x80000000u) ? __uint_as_float(ku ^ 0x80000000u)
                                 : __uint_as_float(~ku);
    ss[head * NN + rank] = f;
    si[head * NN + rank] = (int)(v & 0xffffffffu);
    w0[head * NN + rank] = expf(0.2f * f);
    w1[head * NN + rank] = expf(f);
}

// ============================================================================
// zscan: inclusive prefix (w0) / suffix (w1) scans, shfl-based
// ============================================================================
__global__ void __launch_bounds__(1024)
zscan_kernel(int layer) {
    const int dir = blockIdx.x, head = blockIdx.y;
    const float* w = (layer == 0) ? (dir == 0 ? g_w0_1 : g_w1_1)
                                  : (dir == 0 ? g_w0_2 : g_w1_2);
    float* z = (layer == 0) ? (dir == 0 ? g_z0_1 : g_z1_1)
                            : (dir == 0 ? g_z0_2 : g_z1_2);

    const int tid = threadIdx.x;
    const int lane = tid & 31, warp = tid >> 5;
    __shared__ float wsum[32], woff[32];

    const int i0 = 4 * tid;
    float4 v = *reinterpret_cast<const float4*>(&w[head * NN + i0]);

    if (dir == 0) {
        float p0 = v.x, p1 = p0 + v.y, p2 = p1 + v.z, p3 = p2 + v.w;
        float x = p3;
#pragma unroll
        for (int o = 1; o < 32; o <<= 1) {
            float y = __shfl_up_sync(0xffffffffu, x, o);
            if (lane >= o) x += y;
        }
        float wexcl = x - p3;
        if (lane == 31) wsum[warp] = x;
        __syncthreads();
        if (warp == 0) {
            float t = wsum[lane];
#pragma unroll
            for (int o = 1; o < 32; o <<= 1) {
                float y = __shfl_up_sync(0xffffffffu, t, o);
                if (lane >= o) t += y;
            }
            woff[lane] = t - wsum[lane];
        }
        __syncthreads();
        float off = woff[warp] + wexcl;
        *reinterpret_cast<float4*>(&z[head * NN + i0]) =
            make_float4(p0 + off, p1 + off, p2 + off, p3 + off);
    } else {
        float q3 = v.w, q2 = q3 + v.z, q1 = q2 + v.y, q0 = q1 + v.x;
        float x = q0;
#pragma unroll
        for (int o = 1; o < 32; o <<= 1) {
            float y = __shfl_down_sync(0xffffffffu, x, o);
            if (lane + o < 32) x += y;
        }
        float wexcl = x - q0;
        if (lane == 0) wsum[warp] = x;
        __syncthreads();
        if (warp == 0) {
            float t = wsum[lane];
#pragma unroll
            for (int o = 1; o < 32; o <<= 1) {
                float y = __shfl_down_sync(0xffffffffu, t, o);
                if (lane + o < 32) t += y;
            }
            woff[lane] = t - wsum[lane];
        }
        __syncthreads();
        float off = woff[warp] + wexcl;
        *reinterpret_cast<float4*>(&z[head * NN + i0]) =
            make_float4(q0 + off, q1 + off, q2 + off, q3 + off);
    }
}

// ============================================================================
// ksearch: split points + per-(head,node) scalar coefficients
// ============================================================================
__global__ void __launch_bounds__(256)
ksearch_kernel(int layer, int H) {
    const float* t  = (layer == 0) ? g_t1 : g_t2;
    const float* ss = (layer == 0) ? g_ss1 : g_ss2;
    const float* z0 = (layer == 0) ? g_z0_1 : g_z0_2;
    const float* z1 = (layer == 0) ? g_z1_1 : g_z1_2;
    int*    kk = (layer == 0) ? g_k1 : g_k2;
    float2* aa = (layer == 0) ? g_a1 : g_a2;

    int gid = blockIdx.x * 256 + threadIdx.x;
    if (gid >= H * NN) return;
    int head = gid >> 12;
    const float* ssh = ss + head * NN;
    float tv = t[gid];
    float tau = -tv;
    int pos = 0;
#pragma unroll
    for (int step = NN; step >= 1; step >>= 1) {
        if (pos + step <= NN && __ldg(&ssh[pos + step - 1]) <= tau) pos += step;
    }
    kk[gid] = pos;

    float z0v = (pos > 0)  ? z0[head * NN + pos - 1] : 0.f;
    float z1v = (pos < NN) ? z1[head * NN + pos]     : 0.f;
    float et  = expf(tv);
    float et2 = expf(0.2f * tv);
    float inv = 1.f / (et * z1v + et2 * z0v);
    float a0 = (pos > 0)  ? et2 * inv : 0.f;
    float a1 = (pos < NN) ? et  * inv : 0.f;
    aa[gid] = make_float2(a0, a1);
}

// ============================================================================
// passA: chunked vector scans (MLP=16 gathers)
// ============================================================================
__global__ void __launch_bounds__(CD)
passA_kernel(int layer, int F) {
    const float* h  = (layer == 0) ? g_h1 : g_h2;
    const int*   si = (layer == 0) ? g_si1 : g_si2;
    const float* w0 = (layer == 0) ? g_w0_1 : g_w0_2;
    const float* w1 = (layer == 0) ? g_w1_1 : g_w1_2;
    float* I0 = (layer == 0) ? g_I0_1 : g_I0_2;
    float* S1 = (layer == 0) ? g_S1_1 : g_S1_2;

    const int chunk = blockIdx.x, head = blockIdx.y, dir = blockIdx.z;
    const int c = threadIdx.x;
    const int base = head * NN + chunk * CHUNK;

    __shared__ int   sj[CHUNK];
    __shared__ float sw[CHUNK];
    const float* wsel = (dir == 0) ? w0 : w1;
    for (int r = threadIdx.x; r < CHUNK; r += blockDim.x) {
        sj[r] = si[base + r] * F + head * CD;
        sw[r] = wsel[base + r];
    }
    __syncthreads();

    float acc = 0.f;
    if (dir == 0) {
        float* dst = I0 + (size_t)base * CD + c;
        for (int rr = 0; rr < CHUNK; rr += 16) {
            float v[16];
#pragma unroll
            for (int u = 0; u < 16; u++) v[u] = __ldg(&h[sj[rr + u] + c]);
#pragma unroll
            for (int u = 0; u < 16; u++) {
                acc = fmaf(sw[rr + u], v[u], acc);
                dst[(size_t)(rr + u) * CD] = acc;
            }
        }
    } else {
        float* dst = S1 + (size_t)base * CD + c;
        for (int rr = CHUNK - 16; rr >= 0; rr -= 16) {
            float v[16];
#pragma unroll
            for (int u = 15; u >= 0; u--) v[u] = __ldg(&h[sj[rr + u] + c]);
#pragma unroll
            for (int u = 15; u >= 0; u--) {
                acc = fmaf(sw[rr + u], v[u], acc);
                dst[(size_t)(rr + u) * CD] = acc;
            }
        }
    }
}

// ---------------- cross-chunk offsets ----------------
__global__ void passB_kernel(int layer) {
    const float* I0 = (layer == 0) ? g_I0_1 : g_I0_2;
    const float* S1 = (layer == 0) ? g_S1_1 : g_S1_2;
    float* O0 = (layer == 0) ? g_O0_1 : g_O0_2;
    float* O1 = (layer == 0) ? g_O1_1 : g_O1_2;

    int head = blockIdx.x, c = threadIdx.x;
    float acc = 0.f;
    for (int ch = 0; ch < NCH; ch++) {
        O0[(head * NCH + ch) * CD + c] = acc;
        acc += I0[(head * NN + ch * CHUNK + CHUNK - 1) * CD + c];
    }
    acc = 0.f;
    for (int ch = NCH - 1; ch >= 0; ch--) {
        O1[(head * NCH + ch) * CD + c] = acc;
        acc += S1[(head * NN + ch * CHUNK) * CD + c];
    }
}

// ---------------- lookup: 2 clamped table reads + 2 FMA + elu ----------------
// Layer 0 writes x1 directly as split bf16 (feeds mma GEMM2); layer 1 writes fp32.
__global__ void __launch_bounds__(CD)
lookup_kernel(int layer, const float* __restrict__ bias, int F) {
    const int*    kk = (layer == 0) ? g_k1 : g_k2;
    const float2* aa = (layer == 0) ? g_a1 : g_a2;
    const float* I0 = (layer == 0) ? g_I0_1 : g_I0_2;
    const float* S1 = (layer == 0) ? g_S1_1 : g_S1_2;
    const float* O0 = (layer == 0) ? g_O0_1 : g_O0_2;
    const float* O1 = (layer == 0) ? g_O1_1 : g_O1_2;

    int head = blockIdx.y, c = threadIdx.x;
    float bv = bias[head * CD + c];

#pragma unroll 2
    for (int u = 0; u < 8; u++) {
        int i = blockIdx.x * 8 + u;
        int k = kk[head * NN + i];
        float2 a = aa[head * NN + i];

        int k0i = (k > 0) ? (k - 1) : 0;
        int k1i = (k < NN) ? k : (NN - 1);
        float A0 = I0[(size_t)(head * NN + k0i) * CD + c] +
                   O0[(head * NCH + k0i / CHUNK) * CD + c];
        float A1 = S1[(size_t)(head * NN + k1i) * CD + c] +
                   O1[(head * NCH + k1i / CHUNK) * CD + c];
        float o = fmaf(a.y, A1, fmaf(a.x, A0, bv));
        float x = elu1(o);
        size_t idx = (size_t)i * F + head * CD + c;
        if (layer == 0) {
            __nv_bfloat16 hh = __float2bfloat16(x);
            g_x1H[idx] = hh;
            g_x1L[idx] = __float2bfloat16(x - __bfloat162float(hh));
        } else {
            g_x2[idx] = x;
        }
    }
}

// ---------------- column mean + FC ----------------
__global__ void colpart_kernel() {
    int b = blockIdx.x, c = threadIdx.x;
    float acc = 0.f;
    for (int r = 0; r < NN / 32; r++) acc += g_x2[(b * (NN / 32) + r) * CD + c];
    g_part[b * CD + c] = acc;
}
__global__ void __launch_bounds__(DIN)
colfinal_fc_kernel(const float* __restrict__ fcW, const float* __restrict__ fcb,
                   float* __restrict__ out) {
    __shared__ float m[CD];
    int tid = threadIdx.x;
    if (tid < CD) {
        float a = 0.f;
        for (int b = 0; b < 32; b++) a += g_part[b * CD + tid];
        m[tid] = a * (1.f / (float)NN);
    }
    __syncthreads();
    if (tid < DIN) {
        float acc = fcb[tid];
#pragma unroll 8
        for (int c = 0; c < CD; c++) acc = fmaf(m[c], fcW[c * DIN + tid], acc);
        out[tid] = acc;
    }
}

// ---------------- launch ----------------
extern "C" void kernel_launch(void* const* d_in, const int* in_sizes, int n_in,
                              void* d_out, int out_size) {
    const float* X   = (const float*)d_in[0];
    const float* W1  = (const float*)d_in[1];
    const float* as1 = (const float*)d_in[2];
    const float* ad1 = (const float*)d_in[3];
    const float* b1  = (const float*)d_in[4];
    const float* W2  = (const float*)d_in[5];
    const float* as2 = (const float*)d_in[6];
    const float* ad2 = (const float*)d_in[7];
    const float* b2  = (const float*)d_in[8];
    const float* fcW = (const float*)d_in[9];
    const float* fcb = (const float*)d_in[10];
    float* out = (float*)d_out;

    const int MMA_SMEM = 2 * 4 * TILEB;   // 81920 bytes
    cudaFuncSetAttribute(gemm_mma_kernel,
                         cudaFuncAttributeMaxDynamicSharedMemorySize, MMA_SMEM);

    // Layer 1: split-bf16 mma.sync GEMM (M=4096, K=768, N=512)
    convA_kernel<<<(NN * DIN / 4) / 256, 256>>>(X);
    convB_kernel<<<dim3(DIN / 32, F1 / 32), 256>>>(W1, 0);
    gemm_mma_kernel<<<dim3(NN / 128, HH1), 256, MMA_SMEM>>>(0, as1, ad1);
    sortchunk_kernel<<<dim3(NSC, HH1), 256>>>(0);
    merge_kernel<<<(HH1 * NN) / 256, 256>>>(0, HH1);
    zscan_kernel<<<dim3(2, HH1), 1024>>>(0);
    ksearch_kernel<<<(HH1 * NN) / 256, 256>>>(0, HH1);
    passA_kernel<<<dim3(NCH, HH1, 2), CD>>>(0, F1);
    passB_kernel<<<HH1, CD>>>(0);
    lookup_kernel<<<dim3(NN / 8, HH1), CD>>>(0, b1, F1);

    // Layer 2: split-bf16 mma.sync GEMM (M=4096, K=512, N=128)
    convB_kernel<<<dim3(F1 / 32, CD / 32), 256>>>(W2, 1);
    gemm_mma_kernel<<<dim3(NN / 128, 1), 256, MMA_SMEM>>>(1, as2, ad2);
    sortchunk_kernel<<<dim3(NSC, 1), 256>>>(1);
    merge_kernel<<<NN / 256, 256>>>(1, 1);
    zscan_kernel<<<dim3(2, 1), 1024>>>(1);
    ksearch_kernel<<<NN / 256, 256>>>(1, 1);
    passA_kernel<<<dim3(NCH, 1, 2), CD>>>(1, CD);
    passB_kernel<<<1, CD>>>(1);
    lookup_kernel<<<dim3(NN / 8, 1), CD>>>(1, b2, CD);

    // Mean + FC
    colpart_kernel<<<32, CD>>>();
    colfinal_fc_kernel<<<1, DIN>>>(fcW, fcb, out);
}